// round 4
// baseline (speedup 1.0000x reference)
#include <cuda_runtime.h>

#define BATCH   64
#define NCLS    80
#define RM      16
#define NO      144      // 80 + 4*16
#define A0      6400     // 80x80
#define A1      1600     // 40x40
#define A2      400      // 20x20
#define AT      8400
#define MAXDET  300

typedef unsigned long long ull;

__device__ float g_conf[BATCH * AT];
__device__ int   g_label[BATCH * AT];
__device__ ull   g_topkey[BATCH * MAXDET];
__device__ float g_dist[BATCH * MAXDET * 4];

// ---------------------------------------------------------------------------
// K1: per-anchor class argmax + sigmoid(max). Reads only the 80 class
// channels, vectorized float4: one thread handles 4 consecutive anchors.
// ---------------------------------------------------------------------------
__global__ void k_conf(const float* __restrict__ f0,
                       const float* __restrict__ f1,
                       const float* __restrict__ f2) {
    int q = blockIdx.x * blockDim.x + threadIdx.x;   // quad index
    int b = blockIdx.y;
    if (q >= AT / 4) return;
    int a = q * 4;

    const float* f; int hw, loc;
    if (a < A0)            { f = f0; hw = A0; loc = a; }
    else if (a < A0 + A1)  { f = f1; hw = A1; loc = a - A0; }
    else                   { f = f2; hw = A2; loc = a - A0 - A1; }

    const float4* base = (const float4*)(f + ((size_t)b * NO + 4 * RM) * hw) + (loc >> 2);
    int hw4 = hw >> 2;

    float4 v = base[0];
    float m0 = v.x, m1 = v.y, m2 = v.z, m3 = v.w;
    int l0 = 0, l1 = 0, l2 = 0, l3 = 0;
#pragma unroll 8
    for (int c = 1; c < NCLS; ++c) {
        v = base[(size_t)c * hw4];
        if (v.x > m0) { m0 = v.x; l0 = c; }
        if (v.y > m1) { m1 = v.y; l1 = c; }
        if (v.z > m2) { m2 = v.z; l2 = c; }
        if (v.w > m3) { m3 = v.w; l3 = c; }
    }
    float4 cf;
    cf.x = 1.0f / (1.0f + __expf(-m0));
    cf.y = 1.0f / (1.0f + __expf(-m1));
    cf.z = 1.0f / (1.0f + __expf(-m2));
    cf.w = 1.0f / (1.0f + __expf(-m3));
    *(float4*)&g_conf[b * AT + a] = cf;
    int4 lb; lb.x = l0; lb.y = l1; lb.z = l2; lb.w = l3;
    *(int4*)&g_label[b * AT + a] = lb;
}

// 64-bit key: (monotonic conf bits << 32) | (~index). conf > 0 so the
// monotonic map is OR of the sign bit. Reproduces lax.top_k ordering exactly.
__device__ __forceinline__ ull make_key_s(const float* __restrict__ sconf, int i) {
    unsigned ub = __float_as_uint(sconf[i]) | 0x80000000u;
    return ((ull)ub << 32) | (ull)(0xFFFFFFFFu - (unsigned)i);
}

// ---------------------------------------------------------------------------
// K2: per-batch exact top-300. Radix select (SMEM-cached conf, warp-aggregated
// histogram, early exit) -> collect 300 keys -> rank-by-counting sort ->
// write sorted keys to g_topkey.
// ---------------------------------------------------------------------------
__global__ void __launch_bounds__(1024, 1)
k_topk() {
    __shared__ float s_conf[AT];     // 33.6 KB
    __shared__ int  s_hist[256];
    __shared__ ull  s_keys[MAXDET];
    __shared__ ull  sh_prefix;
    __shared__ int  sh_rank;
    __shared__ int  sh_done;
    __shared__ int  s_cnt;

    const int b    = blockIdx.x;
    const int tid  = threadIdx.x;
    const int lane = tid & 31;
    const int wid  = tid >> 5;

    for (int i = tid; i < AT; i += 1024)
        s_conf[i] = g_conf[b * AT + i];
    if (tid == 0) { sh_prefix = 0ull; sh_rank = MAXDET; sh_done = 0; s_cnt = 0; }
    __syncthreads();

    // ---- radix select with early exit ----
    for (int shift = 56; shift >= 0; shift -= 8) {
        if (tid < 256) s_hist[tid] = 0;
        __syncthreads();
        ull pfx = sh_prefix;
        int hi = shift + 8;
        for (int base = 0; base < AT; base += 1024) {
            int i = base + tid;
            bool act = false; int bin = 0;
            if (i < AT) {
                ull key = make_key_s(s_conf, i);
                act = (hi >= 64) || ((key >> hi) == (pfx >> hi));
                bin = (int)((key >> shift) & 255);
            }
            unsigned am = __ballot_sync(0xFFFFFFFFu, act);
            if (act) {
                unsigned peers = __match_any_sync(am, bin);
                if ((__ffs(peers) - 1) == lane)
                    atomicAdd(&s_hist[bin], __popc(peers));
            }
        }
        __syncthreads();
        if (wid == 0) {
            int base = 255 - lane * 8;           // lane owns 8 descending bins
            int loc[8]; int gs = 0;
#pragma unroll
            for (int t = 0; t < 8; ++t) { loc[t] = s_hist[base - t]; gs += loc[t]; }
            int cum = gs;
#pragma unroll
            for (int o = 1; o < 32; o <<= 1) {
                int v = __shfl_up_sync(0xFFFFFFFFu, cum, o);
                if (lane >= o) cum += v;
            }
            int r = sh_rank;
            bool found = (cum >= r) && ((cum - gs) < r);
            unsigned m = __ballot_sync(0xFFFFFFFFu, found);
            int src = __ffs(m) - 1;
            if (lane == src) {
                int c = cum - gs;
                int d = base, rr = r, cd = 0;
#pragma unroll
                for (int t = 0; t < 8; ++t) {
                    c += loc[t];
                    if (c >= r) { d = base - t; cd = loc[t]; rr = r - (c - loc[t]); break; }
                }
                sh_rank   = rr;
                sh_prefix = pfx | ((ull)d << shift);
                if (cd == rr) sh_done = 1;       // whole bin selected -> pivot exact
            }
        }
        __syncthreads();
        if (sh_done) break;
    }

    // ---- collect exactly 300 keys >= pivot ----
    ull pivot = sh_prefix;
    for (int i = tid; i < AT; i += 1024) {
        ull key = make_key_s(s_conf, i);
        if (key >= pivot) {
            int p = atomicAdd(&s_cnt, 1);
            if (p < MAXDET) s_keys[p] = key;
        }
    }
    __syncthreads();

    // rank-by-counting (keys are all distinct)
    if (tid < MAXDET) {
        ull k = s_keys[tid];
        int rank = 0;
        for (int j = 0; j < MAXDET; ++j) rank += (s_keys[j] > k);
        g_topkey[b * MAXDET + rank] = k;
    }
}

// ---------------------------------------------------------------------------
// K3: DFL softmax decode. One thread per (batch, box, side) task -> 76800
// threads, full-chip MLP for the strided channel gathers.
// ---------------------------------------------------------------------------
__global__ void k_decode(const float* __restrict__ f0,
                         const float* __restrict__ f1,
                         const float* __restrict__ f2) {
    int t = blockIdx.x * blockDim.x + threadIdx.x;
    if (t >= BATCH * MAXDET * 4) return;
    int b   = t / (MAXDET * 4);
    int r   = t - b * (MAXDET * 4);
    int box = r >> 2, s = r & 3;

    ull key = g_topkey[b * MAXDET + box];
    int gidx = (int)(0xFFFFFFFFu - (unsigned)(key & 0xFFFFFFFFull));

    const float* f; int hw, loc;
    if (gidx < A0)           { f = f0; hw = A0; loc = gidx; }
    else if (gidx < A0 + A1) { f = f1; hw = A1; loc = gidx - A0; }
    else                     { f = f2; hw = A2; loc = gidx - A0 - A1; }

    const float* p = f + (size_t)b * NO * hw + (size_t)(s * RM) * hw + loc;
    float x[RM];
    float m = -1e30f;
#pragma unroll
    for (int k = 0; k < RM; ++k) {
        x[k] = __ldg(&p[(size_t)k * hw]);
        if (x[k] > m) m = x[k];
    }
    float se = 0.0f, sk = 0.0f;
#pragma unroll
    for (int k = 0; k < RM; ++k) {
        float e = __expf(x[k] - m);
        se += e;
        sk += e * (float)k;
    }
    g_dist[t] = sk / se;
}

// ---------------------------------------------------------------------------
// K4: per-batch box setup + 300x300 IoU adjacency bitmask + single-warp
// greedy NMS scan + (300, 6) output.
// ---------------------------------------------------------------------------
__global__ void __launch_bounds__(1024, 1)
k_nms(float* __restrict__ out) {
    __shared__ float s_sc[MAXDET];
    __shared__ float s_lab[MAXDET];
    __shared__ float s_cx[MAXDET], s_cy[MAXDET], s_w[MAXDET], s_h[MAXDET];
    __shared__ float s_x1[MAXDET], s_y1[MAXDET], s_x2[MAXDET], s_y2[MAXDET];
    __shared__ float s_area[MAXDET];
    __shared__ unsigned s_adj[MAXDET * 10];   // 300 rows x 10 words
    __shared__ unsigned s_supp[10];

    const int b    = blockIdx.x;
    const int tid  = threadIdx.x;
    const int lane = tid & 31;
    const int wid  = tid >> 5;

    if (tid < MAXDET) {
        ull key = g_topkey[b * MAXDET + tid];
        int gidx = (int)(0xFFFFFFFFu - (unsigned)(key & 0xFFFFFFFFull));
        float conf = __uint_as_float((unsigned)(key >> 32) & 0x7FFFFFFFu);
        s_sc[tid] = conf;

        int loc, W; float stride;
        if (gidx < A0)           { loc = gidx;           W = 80; stride = 8.0f; }
        else if (gidx < A0 + A1) { loc = gidx - A0;      W = 40; stride = 16.0f; }
        else                     { loc = gidx - A0 - A1; W = 20; stride = 32.0f; }

        const float* dd = &g_dist[(b * MAXDET + tid) * 4];
        float d0 = dd[0], d1 = dd[1], d2 = dd[2], d3 = dd[3];

        float gx = (float)(loc % W) + 0.5f;
        float gy = (float)(loc / W) + 0.5f;
        float x1 = gx - d0, y1 = gy - d1;
        float x2 = gx + d2, y2 = gy + d3;
        float cx = (x1 + x2) * 0.5f * stride;
        float cy = (y1 + y2) * 0.5f * stride;
        float w  = (x2 - x1) * stride;
        float h  = (y2 - y1) * stride;
        s_cx[tid] = cx; s_cy[tid] = cy; s_w[tid] = w; s_h[tid] = h;

        float lab = (float)__ldg(&g_label[b * AT + gidx]);
        s_lab[tid] = lab;

        float off = lab * 10000.0f;
        float bx1 = (cx - w * 0.5f) + off;
        float by1 = (cy - h * 0.5f) + off;
        float bx2 = (cx + w * 0.5f) + off;
        float by2 = (cy + h * 0.5f) + off;
        s_x1[tid] = bx1; s_y1[tid] = by1; s_x2[tid] = bx2; s_y2[tid] = by2;
        float aw = bx2 - bx1; if (aw < 0.0f) aw = 0.0f;
        float ah = by2 - by1; if (ah < 0.0f) ah = 0.0f;
        s_area[tid] = aw * ah;
    }
    __syncthreads();

    // validity (supp-at-start) bitmask: warps 0..9, 32 bits each
    if (tid < 320) {
        bool sup0 = (tid < MAXDET) ? !(s_sc[tid] > 0.001f) : false;
        unsigned wv = __ballot_sync(0xFFFFFFFFu, sup0);
        if (lane == 0) s_supp[tid >> 5] = wv;
    }

    // adjacency bitmask (warp per 32-bit word)
    for (int t = wid; t < MAXDET * 10; t += 32) {
        int i = t / 10, w = t - i * 10;
        int j = (w << 5) + lane;
        bool p = false;
        if (j < MAXDET && j > i) {
            float ix1 = fmaxf(s_x1[i], s_x1[j]);
            float iy1 = fmaxf(s_y1[i], s_y1[j]);
            float ix2 = fminf(s_x2[i], s_x2[j]);
            float iy2 = fminf(s_y2[i], s_y2[j]);
            float iw = ix2 - ix1; if (iw < 0.0f) iw = 0.0f;
            float ih = iy2 - iy1; if (ih < 0.0f) ih = 0.0f;
            float inter = iw * ih;
            float iou = inter / (s_area[i] + s_area[j] - inter + 1e-7f);
            p = iou > 0.7f;
        }
        unsigned word = __ballot_sync(0xFFFFFFFFu, p);
        if (lane == 0) s_adj[t] = word;
    }
    __syncthreads();

    // greedy scan in one warp: lane w (w<10) holds supp word w in a register
    if (wid == 0) {
        unsigned supp = (lane < 10) ? s_supp[lane] : 0u;
        unsigned row  = (lane < 10) ? s_adj[lane] : 0u;     // row 0 prefetched
        for (int i = 0; i < MAXDET; ++i) {
            unsigned nrow = 0u;
            if (i + 1 < MAXDET && lane < 10) nrow = s_adj[(i + 1) * 10 + lane];
            unsigned sw = __shfl_sync(0xFFFFFFFFu, supp, i >> 5);
            if (!((sw >> (i & 31)) & 1u)) supp |= row;
            row = nrow;
        }
        if (lane < 10) s_supp[lane] = supp;
    }
    __syncthreads();

    // output (300, 6) rows
    if (tid < MAXDET) {
        bool sup = (s_supp[tid >> 5] >> lane) & 1u;
        float conf = sup ? 0.0f : s_sc[tid];
        float* o = out + ((size_t)b * MAXDET + tid) * 6;
        o[0] = s_cx[tid];
        o[1] = s_cy[tid];
        o[2] = s_w[tid];
        o[3] = s_h[tid];
        o[4] = conf;
        o[5] = s_lab[tid];
    }
}

extern "C" void kernel_launch(void* const* d_in, const int* in_sizes, int n_in,
                              void* d_out, int out_size) {
    const float* f0 = (const float*)d_in[0];
    const float* f1 = (const float*)d_in[1];
    const float* f2 = (const float*)d_in[2];
    float* out = (float*)d_out;

    dim3 g1((AT / 4 + 255) / 256, BATCH);
    k_conf<<<g1, 256>>>(f0, f1, f2);
    k_topk<<<BATCH, 1024>>>();
    int tasks = BATCH * MAXDET * 4;
    k_decode<<<(tasks + 255) / 256, 256>>>(f0, f1, f2);
    k_nms<<<BATCH, 1024>>>(out);
}

// round 5
// speedup vs baseline: 1.0095x; 1.0095x over previous
#include <cuda_runtime.h>

#define BATCH   64
#define NCLS    80
#define RM      16
#define NO      144      // 80 + 4*16
#define A0      6400     // 80x80
#define A1      1600     // 40x40
#define A2      400      // 20x20
#define AT      8400
#define MAXDET  300
#define ADJW    12       // padded words per adjacency row (10 used)

typedef unsigned long long ull;

__device__ float g_conf[BATCH * AT];
__device__ int   g_label[BATCH * AT];
__device__ ull   g_topkey[BATCH * MAXDET];
__device__ float4 g_bcorn[BATCH * MAXDET];   // x1,y1,x2,y2 (class-offset)
__device__ float4 g_bbox [BATCH * MAXDET];   // cx,cy,w,h
__device__ float4 g_bmeta[BATCH * MAXDET];   // area, conf, label, 0
__device__ unsigned g_adj[BATCH * MAXDET * ADJW];

// ---------------------------------------------------------------------------
// K1: per-anchor class argmax + sigmoid(max), float4-vectorized.
// ---------------------------------------------------------------------------
__global__ void k_conf(const float* __restrict__ f0,
                       const float* __restrict__ f1,
                       const float* __restrict__ f2) {
    int q = blockIdx.x * blockDim.x + threadIdx.x;
    int b = blockIdx.y;
    if (q >= AT / 4) return;
    int a = q * 4;

    const float* f; int hw, loc;
    if (a < A0)            { f = f0; hw = A0; loc = a; }
    else if (a < A0 + A1)  { f = f1; hw = A1; loc = a - A0; }
    else                   { f = f2; hw = A2; loc = a - A0 - A1; }

    const float4* base = (const float4*)(f + ((size_t)b * NO + 4 * RM) * hw) + (loc >> 2);
    int hw4 = hw >> 2;

    float4 v = base[0];
    float m0 = v.x, m1 = v.y, m2 = v.z, m3 = v.w;
    int l0 = 0, l1 = 0, l2 = 0, l3 = 0;
#pragma unroll 8
    for (int c = 1; c < NCLS; ++c) {
        v = base[(size_t)c * hw4];
        if (v.x > m0) { m0 = v.x; l0 = c; }
        if (v.y > m1) { m1 = v.y; l1 = c; }
        if (v.z > m2) { m2 = v.z; l2 = c; }
        if (v.w > m3) { m3 = v.w; l3 = c; }
    }
    float4 cf;
    cf.x = 1.0f / (1.0f + __expf(-m0));
    cf.y = 1.0f / (1.0f + __expf(-m1));
    cf.z = 1.0f / (1.0f + __expf(-m2));
    cf.w = 1.0f / (1.0f + __expf(-m3));
    *(float4*)&g_conf[b * AT + a] = cf;
    int4 lb; lb.x = l0; lb.y = l1; lb.z = l2; lb.w = l3;
    *(int4*)&g_label[b * AT + a] = lb;
}

// key = (monotonic conf bits << 32) | (~index); conf>0 so mono map = |signbit.
__device__ __forceinline__ ull make_key_s(const float* __restrict__ sconf, int i) {
    unsigned ub = __float_as_uint(sconf[i]) | 0x80000000u;
    return ((ull)ub << 32) | (ull)(0xFFFFFFFFu - (unsigned)i);
}

// ---------------------------------------------------------------------------
// K2: per-batch exact top-300 (radix select w/ early exit + candidate
// compaction, collect, rank-by-counting sort).
// ---------------------------------------------------------------------------
__global__ void __launch_bounds__(1024, 1)
k_topk() {
    __shared__ float s_conf[AT];          // 33.6 KB
    __shared__ unsigned short s_cand[4096];
    __shared__ int  s_hist[256];
    __shared__ ull  s_keys[MAXDET];
    __shared__ ull  sh_prefix;
    __shared__ int  sh_rank, sh_done, sh_cd;
    __shared__ int  s_cnt, s_nc, s_compact;

    const int b    = blockIdx.x;
    const int tid  = threadIdx.x;
    const int lane = tid & 31;
    const int wid  = tid >> 5;

    for (int i = tid; i < AT; i += 1024)
        s_conf[i] = g_conf[b * AT + i];
    if (tid == 0) {
        sh_prefix = 0ull; sh_rank = MAXDET; sh_done = 0; sh_cd = AT;
        s_cnt = 0; s_nc = 0; s_compact = 0;
    }
    __syncthreads();

    for (int shift = 56; shift >= 0; shift -= 8) {
        if (tid < 256) s_hist[tid] = 0;
        __syncthreads();
        ull pfx = sh_prefix;
        int hi = shift + 8;
        int dom = s_compact ? s_nc : AT;
        for (int base = 0; base < dom; base += 1024) {
            int ci = base + tid;
            bool act = false; int bin = 0;
            if (ci < dom) {
                int i = s_compact ? (int)s_cand[ci] : ci;
                ull key = make_key_s(s_conf, i);
                act = (hi >= 64) || ((key >> hi) == (pfx >> hi));
                bin = (int)((key >> shift) & 255);
            }
            unsigned am = __ballot_sync(0xFFFFFFFFu, act);
            if (act) {
                unsigned peers = __match_any_sync(am, bin);
                if ((__ffs(peers) - 1) == lane)
                    atomicAdd(&s_hist[bin], __popc(peers));
            }
        }
        __syncthreads();
        if (wid == 0) {
            int base = 255 - lane * 8;
            int loc[8]; int gs = 0;
#pragma unroll
            for (int t = 0; t < 8; ++t) { loc[t] = s_hist[base - t]; gs += loc[t]; }
            int cum = gs;
#pragma unroll
            for (int o = 1; o < 32; o <<= 1) {
                int v = __shfl_up_sync(0xFFFFFFFFu, cum, o);
                if (lane >= o) cum += v;
            }
            int r = sh_rank;
            bool found = (cum >= r) && ((cum - gs) < r);
            unsigned m = __ballot_sync(0xFFFFFFFFu, found);
            int src = __ffs(m) - 1;
            if (lane == src) {
                int c = cum - gs;
                int d = base, rr = r, cd = 0;
#pragma unroll
                for (int t = 0; t < 8; ++t) {
                    c += loc[t];
                    if (c >= r) { d = base - t; cd = loc[t]; rr = r - (c - loc[t]); break; }
                }
                sh_rank   = rr;
                sh_prefix = pfx | ((ull)d << shift);
                sh_cd     = cd;
                if (cd == rr) sh_done = 1;
            }
        }
        __syncthreads();
        if (sh_done) break;

        // compact active set once it's small: indices with key>>shift == prefix>>shift
        if (!s_compact && sh_cd <= 4096) {
            ull p2 = sh_prefix;
            for (int i = tid; i < AT; i += 1024) {
                ull key = make_key_s(s_conf, i);
                if ((key >> shift) == (p2 >> shift)) {
                    int p = atomicAdd(&s_nc, 1);
                    if (p < 4096) s_cand[p] = (unsigned short)i;
                }
            }
            __syncthreads();
            if (tid == 0) s_compact = 1;
            __syncthreads();
        }
    }

    // collect exactly 300 keys >= pivot (full scan; pivot is exact)
    ull pivot = sh_prefix;
    for (int i = tid; i < AT; i += 1024) {
        ull key = make_key_s(s_conf, i);
        if (key >= pivot) {
            int p = atomicAdd(&s_cnt, 1);
            if (p < MAXDET) s_keys[p] = key;
        }
    }
    __syncthreads();

    if (tid < MAXDET) {
        ull k = s_keys[tid];
        int rank = 0;
        for (int j = 0; j < MAXDET; ++j) rank += (s_keys[j] > k);
        g_topkey[b * MAXDET + rank] = k;
    }
}

// ---------------------------------------------------------------------------
// K3: DFL decode (thread per (b,box,side)) + fused box assembly by lane s==0
// of each 4-lane box group. Writes corners/cxcywh/meta to global.
// ---------------------------------------------------------------------------
__global__ void k_decode(const float* __restrict__ f0,
                         const float* __restrict__ f1,
                         const float* __restrict__ f2) {
    int t = blockIdx.x * blockDim.x + threadIdx.x;   // grid exact: BATCH*300*4
    int b   = t / (MAXDET * 4);
    int r   = t - b * (MAXDET * 4);
    int box = r >> 2, s = r & 3;
    int lane = threadIdx.x & 31;

    ull key = g_topkey[b * MAXDET + box];
    int gidx = (int)(0xFFFFFFFFu - (unsigned)(key & 0xFFFFFFFFull));

    const float* f; int hw, loc, W; float stride;
    if (gidx < A0)           { f = f0; hw = A0; loc = gidx;           W = 80; stride = 8.0f; }
    else if (gidx < A0 + A1) { f = f1; hw = A1; loc = gidx - A0;      W = 40; stride = 16.0f; }
    else                     { f = f2; hw = A2; loc = gidx - A0 - A1; W = 20; stride = 32.0f; }

    const float* p = f + (size_t)b * NO * hw + (size_t)(s * RM) * hw + loc;
    float x[RM];
    float m = -1e30f;
#pragma unroll
    for (int k = 0; k < RM; ++k) {
        x[k] = __ldg(&p[(size_t)k * hw]);
        if (x[k] > m) m = x[k];
    }
    float se = 0.0f, sk = 0.0f;
#pragma unroll
    for (int k = 0; k < RM; ++k) {
        float e = __expf(x[k] - m);
        se += e;
        sk += e * (float)k;
    }
    float d = sk / se;

    int base_lane = lane & ~3;
    float d0 = __shfl_sync(0xFFFFFFFFu, d, base_lane + 0);
    float d1 = __shfl_sync(0xFFFFFFFFu, d, base_lane + 1);
    float d2 = __shfl_sync(0xFFFFFFFFu, d, base_lane + 2);
    float d3 = __shfl_sync(0xFFFFFFFFu, d, base_lane + 3);

    if (s == 0) {
        float conf = __uint_as_float((unsigned)(key >> 32) & 0x7FFFFFFFu);
        float gx = (float)(loc % W) + 0.5f;
        float gy = (float)(loc / W) + 0.5f;
        float x1 = gx - d0, y1 = gy - d1;
        float x2 = gx + d2, y2 = gy + d3;
        float cx = (x1 + x2) * 0.5f * stride;
        float cy = (y1 + y2) * 0.5f * stride;
        float w  = (x2 - x1) * stride;
        float h  = (y2 - y1) * stride;

        float lab = (float)__ldg(&g_label[b * AT + gidx]);
        float off = lab * 10000.0f;
        float bx1 = (cx - w * 0.5f) + off;
        float by1 = (cy - h * 0.5f) + off;
        float bx2 = (cx + w * 0.5f) + off;
        float by2 = (cy + h * 0.5f) + off;
        float aw = bx2 - bx1; if (aw < 0.0f) aw = 0.0f;
        float ah = by2 - by1; if (ah < 0.0f) ah = 0.0f;

        int o = b * MAXDET + box;
        g_bcorn[o] = make_float4(bx1, by1, bx2, by2);
        g_bbox [o] = make_float4(cx, cy, w, h);
        g_bmeta[o] = make_float4(aw * ah, conf, lab, 0.0f);
    }
}

// ---------------------------------------------------------------------------
// K3b: adjacency bitmask, chip-wide. grid (BATCH, 5): each CTA does 60 rows.
// ---------------------------------------------------------------------------
__global__ void __launch_bounds__(1024, 1)
k_adj() {
    __shared__ float4 s_c[MAXDET];
    __shared__ float  s_a[MAXDET];

    const int b    = blockIdx.x;
    const int tid  = threadIdx.x;
    const int lane = tid & 31;
    const int wid  = tid >> 5;

    if (tid < MAXDET) {
        s_c[tid] = g_bcorn[b * MAXDET + tid];
        s_a[tid] = g_bmeta[b * MAXDET + tid].x;
    }
    __syncthreads();

    const int row0 = blockIdx.y * 60;
    for (int t = wid; t < 60 * ADJW; t += 32) {
        int rl = t / ADJW, w = t - rl * ADJW;
        int i = row0 + rl;
        int j = (w << 5) + lane;
        bool p = false;
        if (w < 10 && j < MAXDET && j > i) {
            float4 ci = s_c[i], cj = s_c[j];
            float ix1 = fmaxf(ci.x, cj.x);
            float iy1 = fmaxf(ci.y, cj.y);
            float ix2 = fminf(ci.z, cj.z);
            float iy2 = fminf(ci.w, cj.w);
            float iw = ix2 - ix1; if (iw < 0.0f) iw = 0.0f;
            float ih = iy2 - iy1; if (ih < 0.0f) ih = 0.0f;
            float inter = iw * ih;
            float iou = inter / (s_a[i] + s_a[j] - inter + 1e-7f);
            p = iou > 0.7f;
        }
        unsigned word = __ballot_sync(0xFFFFFFFFu, p);
        if (lane == 0) g_adj[(b * MAXDET + i) * ADJW + w] = word;
    }
}

// ---------------------------------------------------------------------------
// K4: greedy NMS scan (single thread, register-resident supp) + output.
// ---------------------------------------------------------------------------
__global__ void __launch_bounds__(1024, 1)
k_nms(float* __restrict__ out) {
    __shared__ uint4 s_adj4[MAXDET * 3];   // 300 rows x 12 words
    __shared__ float s_cf[MAXDET];
    __shared__ unsigned s_suppw[10];

    const int b    = blockIdx.x;
    const int tid  = threadIdx.x;
    const int lane = tid & 31;

    if (tid < MAXDET) s_cf[tid] = g_bmeta[b * MAXDET + tid].y;
    const uint4* ga = (const uint4*)&g_adj[b * MAXDET * ADJW];
    for (int t = tid; t < MAXDET * 3; t += 1024) s_adj4[t] = ga[t];
    __syncthreads();

    if (tid < 320) {
        bool sup0 = (tid < MAXDET) ? !(s_cf[tid] > 0.001f) : false;
        unsigned wv = __ballot_sync(0xFFFFFFFFu, sup0);
        if (lane == 0) s_suppw[tid >> 5] = wv;
    }
    __syncthreads();

    if (tid == 0) {
        unsigned supp[10];
#pragma unroll
        for (int k = 0; k < 10; ++k) supp[k] = s_suppw[k];
        uint4 ra = s_adj4[0], rb = s_adj4[1], rc = s_adj4[2];
#pragma unroll
        for (int wb = 0; wb < 10; ++wb) {
            const int nbits = (wb == 9) ? 12 : 32;
            for (int bit = 0; bit < nbits; ++bit) {
                int i = wb * 32 + bit;
                uint4 na = ra, nb = rb, nc = rc;
                if (i + 1 < MAXDET) {
                    na = s_adj4[(i + 1) * 3];
                    nb = s_adj4[(i + 1) * 3 + 1];
                    nc = s_adj4[(i + 1) * 3 + 2];
                }
                if (!((supp[wb] >> bit) & 1u)) {
                    supp[0] |= ra.x; supp[1] |= ra.y; supp[2] |= ra.z; supp[3] |= ra.w;
                    supp[4] |= rb.x; supp[5] |= rb.y; supp[6] |= rb.z; supp[7] |= rb.w;
                    supp[8] |= rc.x; supp[9] |= rc.y;
                }
                ra = na; rb = nb; rc = nc;
            }
        }
#pragma unroll
        for (int k = 0; k < 10; ++k) s_suppw[k] = supp[k];
    }
    __syncthreads();

    if (tid < MAXDET) {
        bool sup = (s_suppw[tid >> 5] >> (tid & 31)) & 1u;
        float4 bb = g_bbox[b * MAXDET + tid];
        float4 mt = g_bmeta[b * MAXDET + tid];
        float conf = sup ? 0.0f : mt.y;
        float* o = out + ((size_t)b * MAXDET + tid) * 6;
        o[0] = bb.x; o[1] = bb.y; o[2] = bb.z; o[3] = bb.w;
        o[4] = conf; o[5] = mt.z;
    }
}

extern "C" void kernel_launch(void* const* d_in, const int* in_sizes, int n_in,
                              void* d_out, int out_size) {
    const float* f0 = (const float*)d_in[0];
    const float* f1 = (const float*)d_in[1];
    const float* f2 = (const float*)d_in[2];
    float* out = (float*)d_out;

    dim3 g1((AT / 4 + 255) / 256, BATCH);
    k_conf<<<g1, 256>>>(f0, f1, f2);
    k_topk<<<BATCH, 1024>>>();
    k_decode<<<BATCH * MAXDET * 4 / 256, 256>>>(f0, f1, f2);
    k_adj<<<dim3(BATCH, 5), 1024>>>();
    k_nms<<<BATCH, 1024>>>(out);
}

// round 6
// speedup vs baseline: 1.1514x; 1.1405x over previous
#include <cuda_runtime.h>

#define BATCH   64
#define NCLS    80
#define RM      16
#define NO      144      // 80 + 4*16
#define A0      6400     // 80x80
#define A1      1600     // 40x40
#define A2      400      // 20x20
#define AT      8400
#define MAXDET  300
#define ADJW    12       // padded words per adjacency row (10 used)

typedef unsigned long long ull;

__device__ float g_conf[BATCH * AT];
__device__ int   g_label[BATCH * AT];
__device__ ull   g_topkey[BATCH * MAXDET];
__device__ float4 g_bcorn[BATCH * MAXDET];   // x1,y1,x2,y2 (class-offset)
__device__ float4 g_bbox [BATCH * MAXDET];   // cx,cy,w,h
__device__ float4 g_bmeta[BATCH * MAXDET];   // area, conf, label, 0
__device__ unsigned g_adj[BATCH * MAXDET * ADJW];

// ---------------------------------------------------------------------------
// K1: per-anchor class argmax + sigmoid(max), float4-vectorized.
// ---------------------------------------------------------------------------
__global__ void k_conf(const float* __restrict__ f0,
                       const float* __restrict__ f1,
                       const float* __restrict__ f2) {
    int q = blockIdx.x * blockDim.x + threadIdx.x;
    int b = blockIdx.y;
    if (q >= AT / 4) return;
    int a = q * 4;

    const float* f; int hw, loc;
    if (a < A0)            { f = f0; hw = A0; loc = a; }
    else if (a < A0 + A1)  { f = f1; hw = A1; loc = a - A0; }
    else                   { f = f2; hw = A2; loc = a - A0 - A1; }

    const float4* base = (const float4*)(f + ((size_t)b * NO + 4 * RM) * hw) + (loc >> 2);
    int hw4 = hw >> 2;

    float4 v = base[0];
    float m0 = v.x, m1 = v.y, m2 = v.z, m3 = v.w;
    int l0 = 0, l1 = 0, l2 = 0, l3 = 0;
#pragma unroll 8
    for (int c = 1; c < NCLS; ++c) {
        v = base[(size_t)c * hw4];
        if (v.x > m0) { m0 = v.x; l0 = c; }
        if (v.y > m1) { m1 = v.y; l1 = c; }
        if (v.z > m2) { m2 = v.z; l2 = c; }
        if (v.w > m3) { m3 = v.w; l3 = c; }
    }
    float4 cf;
    cf.x = 1.0f / (1.0f + __expf(-m0));
    cf.y = 1.0f / (1.0f + __expf(-m1));
    cf.z = 1.0f / (1.0f + __expf(-m2));
    cf.w = 1.0f / (1.0f + __expf(-m3));
    *(float4*)&g_conf[b * AT + a] = cf;
    int4 lb; lb.x = l0; lb.y = l1; lb.z = l2; lb.w = l3;
    *(int4*)&g_label[b * AT + a] = lb;
}

// key = (monotonic conf bits << 32) | (~index); conf>0 so mono map = |signbit.
__device__ __forceinline__ ull make_key_s(const float* __restrict__ sconf, int i) {
    unsigned ub = __float_as_uint(sconf[i]) | 0x80000000u;
    return ((ull)ub << 32) | (ull)(0xFFFFFFFFu - (unsigned)i);
}

// ---------------------------------------------------------------------------
// K2: per-batch exact top-300 (radix select w/ early exit + candidate
// compaction, collect, warp-parallel rank-by-counting sort).
// ---------------------------------------------------------------------------
__global__ void __launch_bounds__(1024, 1)
k_topk() {
    __shared__ float s_conf[AT];          // 33.6 KB
    __shared__ unsigned short s_cand[4096];
    __shared__ int  s_hist[256];
    __shared__ ull  s_keys[MAXDET];
    __shared__ ull  sh_prefix;
    __shared__ int  sh_rank, sh_done, sh_cd;
    __shared__ int  s_cnt, s_nc, s_compact;

    const int b    = blockIdx.x;
    const int tid  = threadIdx.x;
    const int lane = tid & 31;
    const int wid  = tid >> 5;

    for (int i = tid; i < AT; i += 1024)
        s_conf[i] = g_conf[b * AT + i];
    if (tid == 0) {
        sh_prefix = 0ull; sh_rank = MAXDET; sh_done = 0; sh_cd = AT;
        s_cnt = 0; s_nc = 0; s_compact = 0;
    }
    __syncthreads();

    for (int shift = 56; shift >= 0; shift -= 8) {
        if (tid < 256) s_hist[tid] = 0;
        __syncthreads();
        ull pfx = sh_prefix;
        int hi = shift + 8;
        int dom = s_compact ? s_nc : AT;
        for (int base = 0; base < dom; base += 1024) {
            int ci = base + tid;
            bool act = false; int bin = 0;
            if (ci < dom) {
                int i = s_compact ? (int)s_cand[ci] : ci;
                ull key = make_key_s(s_conf, i);
                act = (hi >= 64) || ((key >> hi) == (pfx >> hi));
                bin = (int)((key >> shift) & 255);
            }
            unsigned am = __ballot_sync(0xFFFFFFFFu, act);
            if (act) {
                unsigned peers = __match_any_sync(am, bin);
                if ((__ffs(peers) - 1) == lane)
                    atomicAdd(&s_hist[bin], __popc(peers));
            }
        }
        __syncthreads();
        if (wid == 0) {
            int base = 255 - lane * 8;
            int loc[8]; int gs = 0;
#pragma unroll
            for (int t = 0; t < 8; ++t) { loc[t] = s_hist[base - t]; gs += loc[t]; }
            int cum = gs;
#pragma unroll
            for (int o = 1; o < 32; o <<= 1) {
                int v = __shfl_up_sync(0xFFFFFFFFu, cum, o);
                if (lane >= o) cum += v;
            }
            int r = sh_rank;
            bool found = (cum >= r) && ((cum - gs) < r);
            unsigned m = __ballot_sync(0xFFFFFFFFu, found);
            int src = __ffs(m) - 1;
            if (lane == src) {
                int c = cum - gs;
                int d = base, rr = r, cd = 0;
#pragma unroll
                for (int t = 0; t < 8; ++t) {
                    c += loc[t];
                    if (c >= r) { d = base - t; cd = loc[t]; rr = r - (c - loc[t]); break; }
                }
                sh_rank   = rr;
                sh_prefix = pfx | ((ull)d << shift);
                sh_cd     = cd;
                if (cd == rr) sh_done = 1;
            }
        }
        __syncthreads();
        if (sh_done) break;

        // compact active set once it's small
        if (!s_compact && sh_cd <= 4096) {
            ull p2 = sh_prefix;
            for (int i = tid; i < AT; i += 1024) {
                ull key = make_key_s(s_conf, i);
                if ((key >> shift) == (p2 >> shift)) {
                    int p = atomicAdd(&s_nc, 1);
                    if (p < 4096) s_cand[p] = (unsigned short)i;
                }
            }
            __syncthreads();
            if (tid == 0) s_compact = 1;
            __syncthreads();
        }
    }

    // collect exactly 300 keys >= pivot
    ull pivot = sh_prefix;
    for (int i = tid; i < AT; i += 1024) {
        ull key = make_key_s(s_conf, i);
        if (key >= pivot) {
            int p = atomicAdd(&s_cnt, 1);
            if (p < MAXDET) s_keys[p] = key;
        }
    }
    __syncthreads();

    // warp-parallel rank-by-counting (keys all distinct)
    for (int k = wid; k < MAXDET; k += 32) {
        ull key = s_keys[k];
        int cnt = 0;
        for (int j = lane; j < MAXDET; j += 32) cnt += (s_keys[j] > key);
#pragma unroll
        for (int o = 16; o > 0; o >>= 1)
            cnt += __shfl_down_sync(0xFFFFFFFFu, cnt, o);
        if (lane == 0) g_topkey[b * MAXDET + cnt] = key;
    }
}

// ---------------------------------------------------------------------------
// K3: DFL decode (thread per (b,box,side)) + fused box assembly on lane s==0.
// ---------------------------------------------------------------------------
__global__ void k_decode(const float* __restrict__ f0,
                         const float* __restrict__ f1,
                         const float* __restrict__ f2) {
    int t = blockIdx.x * blockDim.x + threadIdx.x;   // grid exact: BATCH*300*4
    int b   = t / (MAXDET * 4);
    int r   = t - b * (MAXDET * 4);
    int box = r >> 2, s = r & 3;
    int lane = threadIdx.x & 31;

    ull key = g_topkey[b * MAXDET + box];
    int gidx = (int)(0xFFFFFFFFu - (unsigned)(key & 0xFFFFFFFFull));

    const float* f; int hw, loc, W; float stride;
    if (gidx < A0)           { f = f0; hw = A0; loc = gidx;           W = 80; stride = 8.0f; }
    else if (gidx < A0 + A1) { f = f1; hw = A1; loc = gidx - A0;      W = 40; stride = 16.0f; }
    else                     { f = f2; hw = A2; loc = gidx - A0 - A1; W = 20; stride = 32.0f; }

    const float* p = f + (size_t)b * NO * hw + (size_t)(s * RM) * hw + loc;
    float x[RM];
    float m = -1e30f;
#pragma unroll
    for (int k = 0; k < RM; ++k) {
        x[k] = __ldg(&p[(size_t)k * hw]);
        if (x[k] > m) m = x[k];
    }
    float se = 0.0f, sk = 0.0f;
#pragma unroll
    for (int k = 0; k < RM; ++k) {
        float e = __expf(x[k] - m);
        se += e;
        sk += e * (float)k;
    }
    float d = sk / se;

    int base_lane = lane & ~3;
    float d0 = __shfl_sync(0xFFFFFFFFu, d, base_lane + 0);
    float d1 = __shfl_sync(0xFFFFFFFFu, d, base_lane + 1);
    float d2 = __shfl_sync(0xFFFFFFFFu, d, base_lane + 2);
    float d3 = __shfl_sync(0xFFFFFFFFu, d, base_lane + 3);

    if (s == 0) {
        float conf = __uint_as_float((unsigned)(key >> 32) & 0x7FFFFFFFu);
        float gx = (float)(loc % W) + 0.5f;
        float gy = (float)(loc / W) + 0.5f;
        float x1 = gx - d0, y1 = gy - d1;
        float x2 = gx + d2, y2 = gy + d3;
        float cx = (x1 + x2) * 0.5f * stride;
        float cy = (y1 + y2) * 0.5f * stride;
        float w  = (x2 - x1) * stride;
        float h  = (y2 - y1) * stride;

        float lab = (float)__ldg(&g_label[b * AT + gidx]);
        float off = lab * 10000.0f;
        float bx1 = (cx - w * 0.5f) + off;
        float by1 = (cy - h * 0.5f) + off;
        float bx2 = (cx + w * 0.5f) + off;
        float by2 = (cy + h * 0.5f) + off;
        float aw = bx2 - bx1; if (aw < 0.0f) aw = 0.0f;
        float ah = by2 - by1; if (ah < 0.0f) ah = 0.0f;

        int o = b * MAXDET + box;
        g_bcorn[o] = make_float4(bx1, by1, bx2, by2);
        g_bbox [o] = make_float4(cx, cy, w, h);
        g_bmeta[o] = make_float4(aw * ah, conf, lab, 0.0f);
    }
}

// ---------------------------------------------------------------------------
// K3b: adjacency bitmask, warp-per-row, j<=i word skip, guarded division.
// grid (BATCH, 5): 60 rows per CTA, 32 warps.
// ---------------------------------------------------------------------------
__global__ void __launch_bounds__(1024, 1)
k_adj() {
    __shared__ float4 s_c[MAXDET];
    __shared__ float  s_a[MAXDET];

    const int b    = blockIdx.x;
    const int tid  = threadIdx.x;
    const int lane = tid & 31;
    const int wid  = tid >> 5;

    if (tid < MAXDET) {
        s_c[tid] = g_bcorn[b * MAXDET + tid];
        s_a[tid] = g_bmeta[b * MAXDET + tid].x;
    }
    __syncthreads();

    const int row0 = blockIdx.y * 60;
    for (int rl = wid; rl < 60; rl += 32) {
        int i = row0 + rl;
        float4 ci = s_c[i];
        float  ai = s_a[i];
        int w0 = i >> 5;                 // words with all j <= i are zero
        unsigned* row = &g_adj[(b * MAXDET + i) * ADJW];

        for (int w = 0; w < 10; ++w) {
            unsigned word = 0u;
            if (w >= w0) {               // warp-uniform branch
                int j = (w << 5) + lane;
                float inter = 0.0f, den = 1.0f;
                if (j < MAXDET && j > i) {
                    float4 cj = s_c[j];
                    float ix1 = fmaxf(ci.x, cj.x);
                    float iy1 = fmaxf(ci.y, cj.y);
                    float ix2 = fminf(ci.z, cj.z);
                    float iy2 = fminf(ci.w, cj.w);
                    float iw = ix2 - ix1; if (iw < 0.0f) iw = 0.0f;
                    float ih = iy2 - iy1; if (ih < 0.0f) ih = 0.0f;
                    inter = iw * ih;
                    den = ai + s_a[j] - inter + 1e-7f;
                }
                bool p = false;
                if (inter > 0.0f)        // exact: inter==0 -> iou==0 -> false
                    p = (inter / den) > 0.7f;
                word = __ballot_sync(0xFFFFFFFFu, p);
            }
            if (lane == 0) row[w] = word;
        }
        if (lane < 2) row[10 + lane] = 0u;   // padding words
    }
}

// ---------------------------------------------------------------------------
// K4: greedy NMS scan (single thread, register-resident supp) + output.
// ---------------------------------------------------------------------------
__global__ void __launch_bounds__(1024, 1)
k_nms(float* __restrict__ out) {
    __shared__ uint4 s_adj4[MAXDET * 3];   // 300 rows x 12 words
    __shared__ float s_cf[MAXDET];
    __shared__ unsigned s_suppw[10];

    const int b    = blockIdx.x;
    const int tid  = threadIdx.x;
    const int lane = tid & 31;

    if (tid < MAXDET) s_cf[tid] = g_bmeta[b * MAXDET + tid].y;
    const uint4* ga = (const uint4*)&g_adj[b * MAXDET * ADJW];
    for (int t = tid; t < MAXDET * 3; t += 1024) s_adj4[t] = ga[t];
    __syncthreads();

    if (tid < 320) {
        bool sup0 = (tid < MAXDET) ? !(s_cf[tid] > 0.001f) : false;
        unsigned wv = __ballot_sync(0xFFFFFFFFu, sup0);
        if (lane == 0) s_suppw[tid >> 5] = wv;
    }
    __syncthreads();

    if (tid == 0) {
        unsigned supp[10];
#pragma unroll
        for (int k = 0; k < 10; ++k) supp[k] = s_suppw[k];
        uint4 ra = s_adj4[0], rb = s_adj4[1], rc = s_adj4[2];
#pragma unroll
        for (int wb = 0; wb < 10; ++wb) {
            const int nbits = (wb == 9) ? 12 : 32;
            for (int bit = 0; bit < nbits; ++bit) {
                int i = wb * 32 + bit;
                uint4 na = ra, nb = rb, nc = rc;
                if (i + 1 < MAXDET) {
                    na = s_adj4[(i + 1) * 3];
                    nb = s_adj4[(i + 1) * 3 + 1];
                    nc = s_adj4[(i + 1) * 3 + 2];
                }
                if (!((supp[wb] >> bit) & 1u)) {
                    supp[0] |= ra.x; supp[1] |= ra.y; supp[2] |= ra.z; supp[3] |= ra.w;
                    supp[4] |= rb.x; supp[5] |= rb.y; supp[6] |= rb.z; supp[7] |= rb.w;
                    supp[8] |= rc.x; supp[9] |= rc.y;
                }
                ra = na; rb = nb; rc = nc;
            }
        }
#pragma unroll
        for (int k = 0; k < 10; ++k) s_suppw[k] = supp[k];
    }
    __syncthreads();

    if (tid < MAXDET) {
        bool sup = (s_suppw[tid >> 5] >> (tid & 31)) & 1u;
        float4 bb = g_bbox[b * MAXDET + tid];
        float4 mt = g_bmeta[b * MAXDET + tid];
        float conf = sup ? 0.0f : mt.y;
        float* o = out + ((size_t)b * MAXDET + tid) * 6;
        o[0] = bb.x; o[1] = bb.y; o[2] = bb.z; o[3] = bb.w;
        o[4] = conf; o[5] = mt.z;
    }
}

extern "C" void kernel_launch(void* const* d_in, const int* in_sizes, int n_in,
                              void* d_out, int out_size) {
    const float* f0 = (const float*)d_in[0];
    const float* f1 = (const float*)d_in[1];
    const float* f2 = (const float*)d_in[2];
    float* out = (float*)d_out;

    dim3 g1((AT / 4 + 255) / 256, BATCH);
    k_conf<<<g1, 256>>>(f0, f1, f2);
    k_topk<<<BATCH, 1024>>>();
    k_decode<<<BATCH * MAXDET * 4 / 256, 256>>>(f0, f1, f2);
    k_adj<<<dim3(BATCH, 5), 1024>>>();
    k_nms<<<BATCH, 1024>>>(out);
}

// round 9
// speedup vs baseline: 1.1798x; 1.0247x over previous
#include <cuda_runtime.h>

#define BATCH   64
#define NCLS    80
#define RM      16
#define NO      144      // 80 + 4*16
#define A0      6400     // 80x80
#define A1      1600     // 40x40
#define A2      400      // 20x20
#define AT      8400
#define MAXDET  300
#define ADJW    12       // padded words per adjacency row (10 used)

typedef unsigned long long ull;

__device__ float g_conf[BATCH * AT];
__device__ int   g_label[BATCH * AT];
__device__ ull   g_topkey[BATCH * MAXDET];
__device__ float4 g_bcorn[BATCH * MAXDET];   // x1,y1,x2,y2 (class-offset)
__device__ float4 g_bbox [BATCH * MAXDET];   // cx,cy,w,h
__device__ float4 g_bmeta[BATCH * MAXDET];   // area, conf, label, 0

// ---------------------------------------------------------------------------
// K1: per-anchor class argmax + sigmoid(max), float4-vectorized.
// ---------------------------------------------------------------------------
__global__ void k_conf(const float* __restrict__ f0,
                       const float* __restrict__ f1,
                       const float* __restrict__ f2) {
    int q = blockIdx.x * blockDim.x + threadIdx.x;
    int b = blockIdx.y;
    if (q >= AT / 4) return;
    int a = q * 4;

    const float* f; int hw, loc;
    if (a < A0)            { f = f0; hw = A0; loc = a; }
    else if (a < A0 + A1)  { f = f1; hw = A1; loc = a - A0; }
    else                   { f = f2; hw = A2; loc = a - A0 - A1; }

    const float4* base = (const float4*)(f + ((size_t)b * NO + 4 * RM) * hw) + (loc >> 2);
    int hw4 = hw >> 2;

    float4 v = base[0];
    float m0 = v.x, m1 = v.y, m2 = v.z, m3 = v.w;
    int l0 = 0, l1 = 0, l2 = 0, l3 = 0;
#pragma unroll 8
    for (int c = 1; c < NCLS; ++c) {
        v = base[(size_t)c * hw4];
        if (v.x > m0) { m0 = v.x; l0 = c; }
        if (v.y > m1) { m1 = v.y; l1 = c; }
        if (v.z > m2) { m2 = v.z; l2 = c; }
        if (v.w > m3) { m3 = v.w; l3 = c; }
    }
    float4 cf;
    cf.x = 1.0f / (1.0f + __expf(-m0));
    cf.y = 1.0f / (1.0f + __expf(-m1));
    cf.z = 1.0f / (1.0f + __expf(-m2));
    cf.w = 1.0f / (1.0f + __expf(-m3));
    *(float4*)&g_conf[b * AT + a] = cf;
    int4 lb; lb.x = l0; lb.y = l1; lb.z = l2; lb.w = l3;
    *(int4*)&g_label[b * AT + a] = lb;
}

// key = (monotonic conf bits << 32) | (~index); conf>0 so mono map = |signbit.
__device__ __forceinline__ ull key_from(float c, int i) {
    unsigned ub = __float_as_uint(c) | 0x80000000u;
    return ((ull)ub << 32) | (ull)(0xFFFFFFFFu - (unsigned)i);
}

// ---------------------------------------------------------------------------
// K2: per-batch exact top-300. Radix select; pass 1 fused with the
// global->SMEM copy (predicate-safe warp aggregation); candidate compaction
// fused into the pass scan; early exit when the chosen bin completes the
// selection exactly.
// ---------------------------------------------------------------------------
__global__ void __launch_bounds__(1024, 1)
k_topk() {
    __shared__ float s_conf[AT];          // 33.6 KB
    __shared__ unsigned short s_cand[4096];
    __shared__ int  s_hist[256];
    __shared__ ull  s_keys[MAXDET];
    __shared__ ull  sh_prefix;
    __shared__ int  sh_rank, sh_done, sh_cd;
    __shared__ int  s_cnt, s_nc, s_compact;

    const int b    = blockIdx.x;
    const int tid  = threadIdx.x;
    const int lane = tid & 31;
    const int wid  = tid >> 5;

    if (tid == 0) {
        sh_prefix = 0ull; sh_rank = MAXDET; sh_done = 0; sh_cd = AT;
        s_cnt = 0; s_nc = 0; s_compact = 0;
    }
    if (tid < 256) s_hist[tid] = 0;
    __syncthreads();

    // ---- pass 1 (shift=56): copy global->SMEM fused with histogram ----
    // Uniform base-strided loop: every thread executes every iteration; warp
    // intrinsics use a ballot-derived mask (ragged tail safe).
    for (int base = 0; base < AT; base += 1024) {
        int i = base + tid;
        bool in = (i < AT);
        float c = 0.0f;
        int bin = 0;
        if (in) {
            c = g_conf[b * AT + i];
            s_conf[i] = c;
            bin = (int)((__float_as_uint(c) | 0x80000000u) >> 24);
        }
        unsigned am = __ballot_sync(0xFFFFFFFFu, in);
        if (in) {
            unsigned peers = __match_any_sync(am, bin);
            if ((__ffs(peers) - 1) == lane)
                atomicAdd(&s_hist[bin], __popc(peers));
        }
    }
    __syncthreads();

    for (int shift = 56; shift >= 0; shift -= 8) {
        // digit selection from s_hist (warp 0)
        if (wid == 0) {
            int base = 255 - lane * 8;
            int loc[8]; int gs = 0;
#pragma unroll
            for (int t = 0; t < 8; ++t) { loc[t] = s_hist[base - t]; gs += loc[t]; }
            int cum = gs;
#pragma unroll
            for (int o = 1; o < 32; o <<= 1) {
                int v = __shfl_up_sync(0xFFFFFFFFu, cum, o);
                if (lane >= o) cum += v;
            }
            int r = sh_rank;
            bool found = (cum >= r) && ((cum - gs) < r);
            unsigned m = __ballot_sync(0xFFFFFFFFu, found);
            int src = __ffs(m) - 1;
            if (lane == src) {
                int c = cum - gs;
                int d = base, rr = r, cd = 0;
#pragma unroll
                for (int t = 0; t < 8; ++t) {
                    c += loc[t];
                    if (c >= r) { d = base - t; cd = loc[t]; rr = r - (c - loc[t]); break; }
                }
                sh_rank   = rr;
                sh_prefix = sh_prefix | ((ull)d << shift);
                sh_cd     = cd;
                if (cd == rr) sh_done = 1;
            }
        }
        __syncthreads();
        if (sh_done || shift == 0) break;

        // ---- next pass scan: histogram + (maybe) compaction, fused ----
        int nshift = shift - 8;
        int nhi    = shift;
        bool do_compact = (!s_compact) && (sh_cd <= 4096);
        if (tid < 256) s_hist[tid] = 0;
        __syncthreads();
        ull pfx = sh_prefix;
        int dom = s_compact ? s_nc : AT;
        for (int base = 0; base < dom; base += 1024) {
            int ci = base + tid;
            bool act = false; int bin = 0; int idx = 0;
            if (ci < dom) {
                idx = s_compact ? (int)s_cand[ci] : ci;
                ull key = key_from(s_conf[idx], idx);
                act = ((key >> nhi) == (pfx >> nhi));
                bin = (int)((key >> nshift) & 255);
            }
            unsigned am = __ballot_sync(0xFFFFFFFFu, act);
            if (act) {
                unsigned peers = __match_any_sync(am, bin);
                if ((__ffs(peers) - 1) == lane)
                    atomicAdd(&s_hist[bin], __popc(peers));
                if (do_compact) {
                    int p = atomicAdd(&s_nc, 1);
                    if (p < 4096) s_cand[p] = (unsigned short)idx;
                }
            }
        }
        __syncthreads();
        if (do_compact) {
            if (tid == 0) s_compact = 1;
            __syncthreads();
        }
    }

    // ---- collect exactly 300 keys >= pivot (SMEM scan; pivot exact) ----
    ull pivot = sh_prefix;
    for (int i = tid; i < AT; i += 1024) {
        ull key = key_from(s_conf[i], i);
        if (key >= pivot) {
            int p = atomicAdd(&s_cnt, 1);
            if (p < MAXDET) s_keys[p] = key;
        }
    }
    __syncthreads();

    // warp-parallel rank-by-counting (keys all distinct)
    for (int k = wid; k < MAXDET; k += 32) {
        ull key = s_keys[k];
        int cnt = 0;
        for (int j = lane; j < MAXDET; j += 32) cnt += (s_keys[j] > key);
#pragma unroll
        for (int o = 16; o > 0; o >>= 1)
            cnt += __shfl_down_sync(0xFFFFFFFFu, cnt, o);
        if (lane == 0) g_topkey[b * MAXDET + cnt] = key;
    }
}

// ---------------------------------------------------------------------------
// K3: DFL decode (thread per (b,box,side)) + fused box assembly on lane s==0.
// ---------------------------------------------------------------------------
__global__ void k_decode(const float* __restrict__ f0,
                         const float* __restrict__ f1,
                         const float* __restrict__ f2) {
    int t = blockIdx.x * blockDim.x + threadIdx.x;   // grid exact: BATCH*300*4
    int b   = t / (MAXDET * 4);
    int r   = t - b * (MAXDET * 4);
    int box = r >> 2, s = r & 3;
    int lane = threadIdx.x & 31;

    ull key = g_topkey[b * MAXDET + box];
    int gidx = (int)(0xFFFFFFFFu - (unsigned)(key & 0xFFFFFFFFull));

    const float* f; int hw, loc, W; float stride;
    if (gidx < A0)           { f = f0; hw = A0; loc = gidx;           W = 80; stride = 8.0f; }
    else if (gidx < A0 + A1) { f = f1; hw = A1; loc = gidx - A0;      W = 40; stride = 16.0f; }
    else                     { f = f2; hw = A2; loc = gidx - A0 - A1; W = 20; stride = 32.0f; }

    const float* p = f + (size_t)b * NO * hw + (size_t)(s * RM) * hw + loc;
    float x[RM];
    float m = -1e30f;
#pragma unroll
    for (int k = 0; k < RM; ++k) {
        x[k] = __ldg(&p[(size_t)k * hw]);
        if (x[k] > m) m = x[k];
    }
    float se = 0.0f, sk = 0.0f;
#pragma unroll
    for (int k = 0; k < RM; ++k) {
        float e = __expf(x[k] - m);
        se += e;
        sk += e * (float)k;
    }
    float d = sk / se;

    int base_lane = lane & ~3;
    float d0 = __shfl_sync(0xFFFFFFFFu, d, base_lane + 0);
    float d1 = __shfl_sync(0xFFFFFFFFu, d, base_lane + 1);
    float d2 = __shfl_sync(0xFFFFFFFFu, d, base_lane + 2);
    float d3 = __shfl_sync(0xFFFFFFFFu, d, base_lane + 3);

    if (s == 0) {
        float conf = __uint_as_float((unsigned)(key >> 32) & 0x7FFFFFFFu);
        float gx = (float)(loc % W) + 0.5f;
        float gy = (float)(loc / W) + 0.5f;
        float x1 = gx - d0, y1 = gy - d1;
        float x2 = gx + d2, y2 = gy + d3;
        float cx = (x1 + x2) * 0.5f * stride;
        float cy = (y1 + y2) * 0.5f * stride;
        float w  = (x2 - x1) * stride;
        float h  = (y2 - y1) * stride;

        float lab = (float)__ldg(&g_label[b * AT + gidx]);
        float off = lab * 10000.0f;
        float bx1 = (cx - w * 0.5f) + off;
        float by1 = (cy - h * 0.5f) + off;
        float bx2 = (cx + w * 0.5f) + off;
        float by2 = (cy + h * 0.5f) + off;
        float aw = bx2 - bx1; if (aw < 0.0f) aw = 0.0f;
        float ah = by2 - by1; if (ah < 0.0f) ah = 0.0f;

        int o = b * MAXDET + box;
        g_bcorn[o] = make_float4(bx1, by1, bx2, by2);
        g_bbox [o] = make_float4(cx, cy, w, h);
        g_bmeta[o] = make_float4(aw * ah, conf, lab, 0.0f);
    }
}

// ---------------------------------------------------------------------------
// K4: fused adjacency (warp-per-row interleaved, guarded divide) + greedy
// scan (single thread, register-resident supp) + output. One CTA per batch.
// ---------------------------------------------------------------------------
__global__ void __launch_bounds__(1024, 1)
k_nms(float* __restrict__ out) {
    __shared__ float4 s_c[MAXDET];
    __shared__ float  s_a[MAXDET];
    __shared__ float  s_cf[MAXDET];
    __shared__ unsigned s_adj[MAXDET * ADJW];   // 14.4 KB
    __shared__ unsigned s_suppw[10];

    const int b    = blockIdx.x;
    const int tid  = threadIdx.x;
    const int lane = tid & 31;
    const int wid  = tid >> 5;

    if (tid < MAXDET) {
        s_c[tid]  = g_bcorn[b * MAXDET + tid];
        float4 mt = g_bmeta[b * MAXDET + tid];
        s_a[tid]  = mt.x;
        s_cf[tid] = mt.y;
    }
    __syncthreads();

    // adjacency: warp-per-row, interleaved for balance (loop count is
    // warp-uniform; all ballots are full-warp)
    for (int i = wid; i < MAXDET; i += 32) {
        float4 ci = s_c[i];
        float  ai = s_a[i];
        int w0 = i >> 5;                       // words with all j <= i are zero
        unsigned* row = &s_adj[i * ADJW];
        if (lane < w0) row[lane] = 0u;
        if (lane < 2)  row[10 + lane] = 0u;    // padding
        for (int w = w0; w < 10; ++w) {
            int j = (w << 5) + lane;
            float inter = 0.0f, den = 1.0f;
            if (j < MAXDET && j > i) {
                float4 cj = s_c[j];
                float ix1 = fmaxf(ci.x, cj.x);
                float iy1 = fmaxf(ci.y, cj.y);
                float ix2 = fminf(ci.z, cj.z);
                float iy2 = fminf(ci.w, cj.w);
                float iw = ix2 - ix1; if (iw < 0.0f) iw = 0.0f;
                float ih = iy2 - iy1; if (ih < 0.0f) ih = 0.0f;
                inter = iw * ih;
                den = ai + s_a[j] - inter + 1e-7f;
            }
            bool p = false;
            if (inter > 0.0f)                   // exact: inter==0 -> iou==0
                p = (inter / den) > 0.7f;
            unsigned word = __ballot_sync(0xFFFFFFFFu, p);
            if (lane == 0) row[w] = word;
        }
    }

    // validity (supp-at-start) bitmask (warps 0..9, full-warp ballots)
    if (tid < 320) {
        bool sup0 = (tid < MAXDET) ? !(s_cf[tid] > 0.001f) : false;
        unsigned wv = __ballot_sync(0xFFFFFFFFu, sup0);
        if (lane == 0) s_suppw[tid >> 5] = wv;
    }
    __syncthreads();

    // greedy scan: single thread, supp in registers, rows prefetched
    if (tid == 0) {
        const uint4* adj4 = (const uint4*)s_adj;
        unsigned supp[10];
#pragma unroll
        for (int k = 0; k < 10; ++k) supp[k] = s_suppw[k];
        uint4 ra = adj4[0], rb = adj4[1], rc = adj4[2];
#pragma unroll
        for (int wb = 0; wb < 10; ++wb) {
            const int nbits = (wb == 9) ? 12 : 32;
            for (int bit = 0; bit < nbits; ++bit) {
                int i = wb * 32 + bit;
                uint4 na = ra, nb = rb, nc = rc;
                if (i + 1 < MAXDET) {
                    na = adj4[(i + 1) * 3];
                    nb = adj4[(i + 1) * 3 + 1];
                    nc = adj4[(i + 1) * 3 + 2];
                }
                if (!((supp[wb] >> bit) & 1u)) {
                    supp[0] |= ra.x; supp[1] |= ra.y; supp[2] |= ra.z; supp[3] |= ra.w;
                    supp[4] |= rb.x; supp[5] |= rb.y; supp[6] |= rb.z; supp[7] |= rb.w;
                    supp[8] |= rc.x; supp[9] |= rc.y;
                }
                ra = na; rb = nb; rc = nc;
            }
        }
#pragma unroll
        for (int k = 0; k < 10; ++k) s_suppw[k] = supp[k];
    }
    __syncthreads();

    if (tid < MAXDET) {
        bool sup = (s_suppw[tid >> 5] >> (tid & 31)) & 1u;
        float4 bb = g_bbox[b * MAXDET + tid];
        float4 mt = g_bmeta[b * MAXDET + tid];
        float conf = sup ? 0.0f : mt.y;
        float* o = out + ((size_t)b * MAXDET + tid) * 6;
        o[0] = bb.x; o[1] = bb.y; o[2] = bb.z; o[3] = bb.w;
        o[4] = conf; o[5] = mt.z;
    }
}

extern "C" void kernel_launch(void* const* d_in, const int* in_sizes, int n_in,
                              void* d_out, int out_size) {
    const float* f0 = (const float*)d_in[0];
    const float* f1 = (const float*)d_in[1];
    const float* f2 = (const float*)d_in[2];
    float* out = (float*)d_out;

    dim3 g1((AT / 4 + 255) / 256, BATCH);
    k_conf<<<g1, 256>>>(f0, f1, f2);
    k_topk<<<BATCH, 1024>>>();
    k_decode<<<BATCH * MAXDET * 4 / 256, 256>>>(f0, f1, f2);
    k_nms<<<BATCH, 1024>>>(out);
}

// round 10
// speedup vs baseline: 1.3129x; 1.1128x over previous
#include <cuda_runtime.h>

#define BATCH   64
#define NCLS    80
#define RM      16
#define NO      144      // 80 + 4*16
#define A0      6400     // 80x80
#define A1      1600     // 40x40
#define A2      400      // 20x20
#define AT      8400
#define MAXDET  300
#define ADJW    12       // padded words per adjacency row (10 used)

typedef unsigned long long ull;

__device__ float g_conf[BATCH * AT];
__device__ int   g_label[BATCH * AT];
__device__ ull   g_topkey[BATCH * MAXDET];
__device__ float4 g_bcorn[BATCH * MAXDET];   // x1,y1,x2,y2 (class-offset)
__device__ float4 g_bbox [BATCH * MAXDET];   // cx,cy,w,h
__device__ float4 g_bmeta[BATCH * MAXDET];   // area, conf, label, 0

// ---------------------------------------------------------------------------
// K1: per-anchor class argmax + sigmoid(max), float4-vectorized.
// ---------------------------------------------------------------------------
__global__ void k_conf(const float* __restrict__ f0,
                       const float* __restrict__ f1,
                       const float* __restrict__ f2) {
    int q = blockIdx.x * blockDim.x + threadIdx.x;
    int b = blockIdx.y;
    if (q >= AT / 4) return;
    int a = q * 4;

    const float* f; int hw, loc;
    if (a < A0)            { f = f0; hw = A0; loc = a; }
    else if (a < A0 + A1)  { f = f1; hw = A1; loc = a - A0; }
    else                   { f = f2; hw = A2; loc = a - A0 - A1; }

    const float4* base = (const float4*)(f + ((size_t)b * NO + 4 * RM) * hw) + (loc >> 2);
    int hw4 = hw >> 2;

    float4 v = base[0];
    float m0 = v.x, m1 = v.y, m2 = v.z, m3 = v.w;
    int l0 = 0, l1 = 0, l2 = 0, l3 = 0;
#pragma unroll 8
    for (int c = 1; c < NCLS; ++c) {
        v = base[(size_t)c * hw4];
        if (v.x > m0) { m0 = v.x; l0 = c; }
        if (v.y > m1) { m1 = v.y; l1 = c; }
        if (v.z > m2) { m2 = v.z; l2 = c; }
        if (v.w > m3) { m3 = v.w; l3 = c; }
    }
    float4 cf;
    cf.x = 1.0f / (1.0f + __expf(-m0));
    cf.y = 1.0f / (1.0f + __expf(-m1));
    cf.z = 1.0f / (1.0f + __expf(-m2));
    cf.w = 1.0f / (1.0f + __expf(-m3));
    *(float4*)&g_conf[b * AT + a] = cf;
    int4 lb; lb.x = l0; lb.y = l1; lb.z = l2; lb.w = l3;
    *(int4*)&g_label[b * AT + a] = lb;
}

// key = (monotonic conf bits << 32) | (~index); conf>0 so mono map = |signbit.
__device__ __forceinline__ ull key_from(float c, int i) {
    unsigned ub = __float_as_uint(c) | 0x80000000u;
    return ((ull)ub << 32) | (ull)(0xFFFFFFFFu - (unsigned)i);
}

// ---------------------------------------------------------------------------
// K2: per-batch exact top-300. Radix select; pass 1 fused with the
// global->SMEM copy (predicate-safe warp aggregation); candidate compaction
// fused into the pass scan; early exit when the chosen bin completes the
// selection exactly.
// ---------------------------------------------------------------------------
__global__ void __launch_bounds__(1024, 1)
k_topk() {
    __shared__ float s_conf[AT];          // 33.6 KB
    __shared__ unsigned short s_cand[4096];
    __shared__ int  s_hist[256];
    __shared__ ull  s_keys[MAXDET];
    __shared__ ull  sh_prefix;
    __shared__ int  sh_rank, sh_done, sh_cd;
    __shared__ int  s_cnt, s_nc, s_compact;

    const int b    = blockIdx.x;
    const int tid  = threadIdx.x;
    const int lane = tid & 31;
    const int wid  = tid >> 5;

    if (tid == 0) {
        sh_prefix = 0ull; sh_rank = MAXDET; sh_done = 0; sh_cd = AT;
        s_cnt = 0; s_nc = 0; s_compact = 0;
    }
    if (tid < 256) s_hist[tid] = 0;
    __syncthreads();

    // ---- pass 1 (shift=56): copy global->SMEM fused with histogram ----
    for (int base = 0; base < AT; base += 1024) {
        int i = base + tid;
        bool in = (i < AT);
        float c = 0.0f;
        int bin = 0;
        if (in) {
            c = g_conf[b * AT + i];
            s_conf[i] = c;
            bin = (int)((__float_as_uint(c) | 0x80000000u) >> 24);
        }
        unsigned am = __ballot_sync(0xFFFFFFFFu, in);
        if (in) {
            unsigned peers = __match_any_sync(am, bin);
            if ((__ffs(peers) - 1) == lane)
                atomicAdd(&s_hist[bin], __popc(peers));
        }
    }
    __syncthreads();

    for (int shift = 56; shift >= 0; shift -= 8) {
        // digit selection from s_hist (warp 0)
        if (wid == 0) {
            int base = 255 - lane * 8;
            int loc[8]; int gs = 0;
#pragma unroll
            for (int t = 0; t < 8; ++t) { loc[t] = s_hist[base - t]; gs += loc[t]; }
            int cum = gs;
#pragma unroll
            for (int o = 1; o < 32; o <<= 1) {
                int v = __shfl_up_sync(0xFFFFFFFFu, cum, o);
                if (lane >= o) cum += v;
            }
            int r = sh_rank;
            bool found = (cum >= r) && ((cum - gs) < r);
            unsigned m = __ballot_sync(0xFFFFFFFFu, found);
            int src = __ffs(m) - 1;
            if (lane == src) {
                int c = cum - gs;
                int d = base, rr = r, cd = 0;
#pragma unroll
                for (int t = 0; t < 8; ++t) {
                    c += loc[t];
                    if (c >= r) { d = base - t; cd = loc[t]; rr = r - (c - loc[t]); break; }
                }
                sh_rank   = rr;
                sh_prefix = sh_prefix | ((ull)d << shift);
                sh_cd     = cd;
                if (cd == rr) sh_done = 1;
            }
        }
        __syncthreads();
        if (sh_done || shift == 0) break;

        // ---- next pass scan: histogram + (maybe) compaction, fused ----
        int nshift = shift - 8;
        int nhi    = shift;
        bool do_compact = (!s_compact) && (sh_cd <= 4096);
        if (tid < 256) s_hist[tid] = 0;
        __syncthreads();
        ull pfx = sh_prefix;
        int dom = s_compact ? s_nc : AT;
        for (int base = 0; base < dom; base += 1024) {
            int ci = base + tid;
            bool act = false; int bin = 0; int idx = 0;
            if (ci < dom) {
                idx = s_compact ? (int)s_cand[ci] : ci;
                ull key = key_from(s_conf[idx], idx);
                act = ((key >> nhi) == (pfx >> nhi));
                bin = (int)((key >> nshift) & 255);
            }
            unsigned am = __ballot_sync(0xFFFFFFFFu, act);
            if (act) {
                unsigned peers = __match_any_sync(am, bin);
                if ((__ffs(peers) - 1) == lane)
                    atomicAdd(&s_hist[bin], __popc(peers));
                if (do_compact) {
                    int p = atomicAdd(&s_nc, 1);
                    if (p < 4096) s_cand[p] = (unsigned short)idx;
                }
            }
        }
        __syncthreads();
        if (do_compact) {
            if (tid == 0) s_compact = 1;
            __syncthreads();
        }
    }

    // ---- collect exactly 300 keys >= pivot (SMEM scan; pivot exact) ----
    ull pivot = sh_prefix;
    for (int i = tid; i < AT; i += 1024) {
        ull key = key_from(s_conf[i], i);
        if (key >= pivot) {
            int p = atomicAdd(&s_cnt, 1);
            if (p < MAXDET) s_keys[p] = key;
        }
    }
    __syncthreads();

    // warp-parallel rank-by-counting (keys all distinct)
    for (int k = wid; k < MAXDET; k += 32) {
        ull key = s_keys[k];
        int cnt = 0;
        for (int j = lane; j < MAXDET; j += 32) cnt += (s_keys[j] > key);
#pragma unroll
        for (int o = 16; o > 0; o >>= 1)
            cnt += __shfl_down_sync(0xFFFFFFFFu, cnt, o);
        if (lane == 0) g_topkey[b * MAXDET + cnt] = key;
    }
}

// ---------------------------------------------------------------------------
// K3: DFL decode (thread per (b,box,side)) + fused box assembly on lane s==0.
// ---------------------------------------------------------------------------
__global__ void k_decode(const float* __restrict__ f0,
                         const float* __restrict__ f1,
                         const float* __restrict__ f2) {
    int t = blockIdx.x * blockDim.x + threadIdx.x;   // grid exact: BATCH*300*4
    int b   = t / (MAXDET * 4);
    int r   = t - b * (MAXDET * 4);
    int box = r >> 2, s = r & 3;
    int lane = threadIdx.x & 31;

    ull key = g_topkey[b * MAXDET + box];
    int gidx = (int)(0xFFFFFFFFu - (unsigned)(key & 0xFFFFFFFFull));

    const float* f; int hw, loc, W; float stride;
    if (gidx < A0)           { f = f0; hw = A0; loc = gidx;           W = 80; stride = 8.0f; }
    else if (gidx < A0 + A1) { f = f1; hw = A1; loc = gidx - A0;      W = 40; stride = 16.0f; }
    else                     { f = f2; hw = A2; loc = gidx - A0 - A1; W = 20; stride = 32.0f; }

    const float* p = f + (size_t)b * NO * hw + (size_t)(s * RM) * hw + loc;
    float x[RM];
    float m = -1e30f;
#pragma unroll
    for (int k = 0; k < RM; ++k) {
        x[k] = __ldg(&p[(size_t)k * hw]);
        if (x[k] > m) m = x[k];
    }
    float se = 0.0f, sk = 0.0f;
#pragma unroll
    for (int k = 0; k < RM; ++k) {
        float e = __expf(x[k] - m);
        se += e;
        sk += e * (float)k;
    }
    float d = sk / se;

    int base_lane = lane & ~3;
    float d0 = __shfl_sync(0xFFFFFFFFu, d, base_lane + 0);
    float d1 = __shfl_sync(0xFFFFFFFFu, d, base_lane + 1);
    float d2 = __shfl_sync(0xFFFFFFFFu, d, base_lane + 2);
    float d3 = __shfl_sync(0xFFFFFFFFu, d, base_lane + 3);

    if (s == 0) {
        float conf = __uint_as_float((unsigned)(key >> 32) & 0x7FFFFFFFu);
        float gx = (float)(loc % W) + 0.5f;
        float gy = (float)(loc / W) + 0.5f;
        float x1 = gx - d0, y1 = gy - d1;
        float x2 = gx + d2, y2 = gy + d3;
        float cx = (x1 + x2) * 0.5f * stride;
        float cy = (y1 + y2) * 0.5f * stride;
        float w  = (x2 - x1) * stride;
        float h  = (y2 - y1) * stride;

        float lab = (float)__ldg(&g_label[b * AT + gidx]);
        float off = lab * 10000.0f;
        float bx1 = (cx - w * 0.5f) + off;
        float by1 = (cy - h * 0.5f) + off;
        float bx2 = (cx + w * 0.5f) + off;
        float by2 = (cy + h * 0.5f) + off;
        float aw = bx2 - bx1; if (aw < 0.0f) aw = 0.0f;
        float ah = by2 - by1; if (ah < 0.0f) ah = 0.0f;

        int o = b * MAXDET + box;
        g_bcorn[o] = make_float4(bx1, by1, bx2, by2);
        g_bbox [o] = make_float4(cx, cy, w, h);
        g_bmeta[o] = make_float4(aw * ah, conf, lab, 0.0f);
    }
}

// ---------------------------------------------------------------------------
// K4: fused adjacency (warp-per-row interleaved, guarded divide, nonzero-row
// mask) + sparse greedy scan (single thread, ffs over nonzero unsuppressed
// rows only) + output. One CTA per batch.
// ---------------------------------------------------------------------------
__global__ void __launch_bounds__(1024, 1)
k_nms(float* __restrict__ out) {
    __shared__ float4 s_c[MAXDET];
    __shared__ float  s_a[MAXDET];
    __shared__ float  s_cf[MAXDET];
    __shared__ unsigned s_adj[MAXDET * ADJW];   // 14.4 KB
    __shared__ unsigned s_suppw[10];
    __shared__ unsigned s_nz[10];               // rows with nonzero adjacency

    const int b    = blockIdx.x;
    const int tid  = threadIdx.x;
    const int lane = tid & 31;
    const int wid  = tid >> 5;

    if (tid < 10) s_nz[tid] = 0u;
    if (tid < MAXDET) {
        s_c[tid]  = g_bcorn[b * MAXDET + tid];
        float4 mt = g_bmeta[b * MAXDET + tid];
        s_a[tid]  = mt.x;
        s_cf[tid] = mt.y;
    }
    __syncthreads();

    // adjacency: warp-per-row, interleaved for balance; accumulate row-any
    for (int i = wid; i < MAXDET; i += 32) {
        float4 ci = s_c[i];
        float  ai = s_a[i];
        int w0 = i >> 5;                       // words with all j <= i are zero
        unsigned* row = &s_adj[i * ADJW];
        if (lane < w0) row[lane] = 0u;
        if (lane < 2)  row[10 + lane] = 0u;    // padding
        unsigned acc = 0u;
        for (int w = w0; w < 10; ++w) {
            int j = (w << 5) + lane;
            float inter = 0.0f, den = 1.0f;
            if (j < MAXDET && j > i) {
                float4 cj = s_c[j];
                float ix1 = fmaxf(ci.x, cj.x);
                float iy1 = fmaxf(ci.y, cj.y);
                float ix2 = fminf(ci.z, cj.z);
                float iy2 = fminf(ci.w, cj.w);
                float iw = ix2 - ix1; if (iw < 0.0f) iw = 0.0f;
                float ih = iy2 - iy1; if (ih < 0.0f) ih = 0.0f;
                inter = iw * ih;
                den = ai + s_a[j] - inter + 1e-7f;
            }
            bool p = false;
            if (inter > 0.0f)                   // exact: inter==0 -> iou==0
                p = (inter / den) > 0.7f;
            unsigned word = __ballot_sync(0xFFFFFFFFu, p);
            acc |= word;
            if (lane == 0) row[w] = word;
        }
        if (lane == 0 && acc)
            atomicOr(&s_nz[i >> 5], 1u << (i & 31));
    }

    // validity (supp-at-start) bitmask (warps 0..9, full-warp ballots)
    if (tid < 320) {
        bool sup0 = (tid < MAXDET) ? !(s_cf[tid] > 0.001f) : false;
        unsigned wv = __ballot_sync(0xFFFFFFFFu, sup0);
        if (lane == 0) s_suppw[tid >> 5] = wv;
    }
    __syncthreads();

    // sparse greedy scan: only rows with nonzero adjacency can change supp.
    // Process them in ascending index order; a row's OR only sets bits j>i,
    // so re-masking rem with ~supp[w] after each OR preserves greedy order.
    if (tid == 0) {
        unsigned supp[10];
#pragma unroll
        for (int k = 0; k < 10; ++k) supp[k] = s_suppw[k];
#pragma unroll
        for (int w = 0; w < 10; ++w) {
            unsigned rem = s_nz[w] & ~supp[w];
            while (rem) {
                int bit = __ffs(rem) - 1;
                const uint4* r4 = (const uint4*)&s_adj[((w << 5) + bit) * ADJW];
                uint4 ra = r4[0], rb = r4[1], rc = r4[2];
                supp[0] |= ra.x; supp[1] |= ra.y; supp[2] |= ra.z; supp[3] |= ra.w;
                supp[4] |= rb.x; supp[5] |= rb.y; supp[6] |= rb.z; supp[7] |= rb.w;
                supp[8] |= rc.x; supp[9] |= rc.y;
                rem &= ~(1u << bit);
                rem &= ~supp[w];
            }
        }
#pragma unroll
        for (int k = 0; k < 10; ++k) s_suppw[k] = supp[k];
    }
    __syncthreads();

    if (tid < MAXDET) {
        bool sup = (s_suppw[tid >> 5] >> (tid & 31)) & 1u;
        float4 bb = g_bbox[b * MAXDET + tid];
        float4 mt = g_bmeta[b * MAXDET + tid];
        float conf = sup ? 0.0f : mt.y;
        float* o = out + ((size_t)b * MAXDET + tid) * 6;
        o[0] = bb.x; o[1] = bb.y; o[2] = bb.z; o[3] = bb.w;
        o[4] = conf; o[5] = mt.z;
    }
}

extern "C" void kernel_launch(void* const* d_in, const int* in_sizes, int n_in,
                              void* d_out, int out_size) {
    const float* f0 = (const float*)d_in[0];
    const float* f1 = (const float*)d_in[1];
    const float* f2 = (const float*)d_in[2];
    float* out = (float*)d_out;

    dim3 g1((AT / 4 + 255) / 256, BATCH);
    k_conf<<<g1, 256>>>(f0, f1, f2);
    k_topk<<<BATCH, 1024>>>();
    k_decode<<<BATCH * MAXDET * 4 / 256, 256>>>(f0, f1, f2);
    k_nms<<<BATCH, 1024>>>(out);
}

// round 11
// speedup vs baseline: 1.4337x; 1.0920x over previous
#include <cuda_runtime.h>

#define BATCH   64
#define NCLS    80
#define RM      16
#define NO      144      // 80 + 4*16
#define A0      6400     // 80x80
#define A1      1600     // 40x40
#define A2      400      // 20x20
#define AT      8400
#define MAXDET  300
#define ADJW    12       // padded words per adjacency row (10 used)

typedef unsigned long long ull;

__device__ float g_conf[BATCH * AT];
__device__ int   g_label[BATCH * AT];
__device__ ull   g_topkey[BATCH * MAXDET];
__device__ float4 g_bcorn[BATCH * MAXDET];   // x1,y1,x2,y2 (class-offset)
__device__ float4 g_bbox [BATCH * MAXDET];   // cx,cy,w,h
__device__ float4 g_bmeta[BATCH * MAXDET];   // area, conf, label, 0

// ---------------------------------------------------------------------------
// K1: per-anchor class argmax + sigmoid(max), float4-vectorized.
// ---------------------------------------------------------------------------
__global__ void k_conf(const float* __restrict__ f0,
                       const float* __restrict__ f1,
                       const float* __restrict__ f2) {
    int q = blockIdx.x * blockDim.x + threadIdx.x;
    int b = blockIdx.y;
    if (q >= AT / 4) return;
    int a = q * 4;

    const float* f; int hw, loc;
    if (a < A0)            { f = f0; hw = A0; loc = a; }
    else if (a < A0 + A1)  { f = f1; hw = A1; loc = a - A0; }
    else                   { f = f2; hw = A2; loc = a - A0 - A1; }

    const float4* base = (const float4*)(f + ((size_t)b * NO + 4 * RM) * hw) + (loc >> 2);
    int hw4 = hw >> 2;

    float4 v = base[0];
    float m0 = v.x, m1 = v.y, m2 = v.z, m3 = v.w;
    int l0 = 0, l1 = 0, l2 = 0, l3 = 0;
#pragma unroll 8
    for (int c = 1; c < NCLS; ++c) {
        v = base[(size_t)c * hw4];
        if (v.x > m0) { m0 = v.x; l0 = c; }
        if (v.y > m1) { m1 = v.y; l1 = c; }
        if (v.z > m2) { m2 = v.z; l2 = c; }
        if (v.w > m3) { m3 = v.w; l3 = c; }
    }
    float4 cf;
    cf.x = 1.0f / (1.0f + __expf(-m0));
    cf.y = 1.0f / (1.0f + __expf(-m1));
    cf.z = 1.0f / (1.0f + __expf(-m2));
    cf.w = 1.0f / (1.0f + __expf(-m3));
    *(float4*)&g_conf[b * AT + a] = cf;
    int4 lb; lb.x = l0; lb.y = l1; lb.z = l2; lb.w = l3;
    *(int4*)&g_label[b * AT + a] = lb;
}

// key = (monotonic conf bits << 32) | (~index); conf>0 so mono map = |signbit.
__device__ __forceinline__ ull key_from(float c, int i) {
    unsigned ub = __float_as_uint(c) | 0x80000000u;
    return ((ull)ub << 32) | (ull)(0xFFFFFFFFu - (unsigned)i);
}

// ---------------------------------------------------------------------------
// K2: per-batch exact top-300. Radix select; pass 1 fused with the
// global->SMEM copy (predicate-safe warp aggregation); candidate compaction
// fused into the pass scan; early exit when the chosen bin completes the
// selection exactly.
// ---------------------------------------------------------------------------
__global__ void __launch_bounds__(1024, 1)
k_topk() {
    __shared__ float s_conf[AT];          // 33.6 KB
    __shared__ unsigned short s_cand[4096];
    __shared__ int  s_hist[256];
    __shared__ ull  s_keys[MAXDET];
    __shared__ ull  sh_prefix;
    __shared__ int  sh_rank, sh_done, sh_cd;
    __shared__ int  s_cnt, s_nc, s_compact;

    const int b    = blockIdx.x;
    const int tid  = threadIdx.x;
    const int lane = tid & 31;
    const int wid  = tid >> 5;

    if (tid == 0) {
        sh_prefix = 0ull; sh_rank = MAXDET; sh_done = 0; sh_cd = AT;
        s_cnt = 0; s_nc = 0; s_compact = 0;
    }
    if (tid < 256) s_hist[tid] = 0;
    __syncthreads();

    // ---- pass 1 (shift=56): copy global->SMEM fused with histogram ----
    for (int base = 0; base < AT; base += 1024) {
        int i = base + tid;
        bool in = (i < AT);
        float c = 0.0f;
        int bin = 0;
        if (in) {
            c = g_conf[b * AT + i];
            s_conf[i] = c;
            bin = (int)((__float_as_uint(c) | 0x80000000u) >> 24);
        }
        unsigned am = __ballot_sync(0xFFFFFFFFu, in);
        if (in) {
            unsigned peers = __match_any_sync(am, bin);
            if ((__ffs(peers) - 1) == lane)
                atomicAdd(&s_hist[bin], __popc(peers));
        }
    }
    __syncthreads();

    for (int shift = 56; shift >= 0; shift -= 8) {
        // digit selection from s_hist (warp 0)
        if (wid == 0) {
            int base = 255 - lane * 8;
            int loc[8]; int gs = 0;
#pragma unroll
            for (int t = 0; t < 8; ++t) { loc[t] = s_hist[base - t]; gs += loc[t]; }
            int cum = gs;
#pragma unroll
            for (int o = 1; o < 32; o <<= 1) {
                int v = __shfl_up_sync(0xFFFFFFFFu, cum, o);
                if (lane >= o) cum += v;
            }
            int r = sh_rank;
            bool found = (cum >= r) && ((cum - gs) < r);
            unsigned m = __ballot_sync(0xFFFFFFFFu, found);
            int src = __ffs(m) - 1;
            if (lane == src) {
                int c = cum - gs;
                int d = base, rr = r, cd = 0;
#pragma unroll
                for (int t = 0; t < 8; ++t) {
                    c += loc[t];
                    if (c >= r) { d = base - t; cd = loc[t]; rr = r - (c - loc[t]); break; }
                }
                sh_rank   = rr;
                sh_prefix = sh_prefix | ((ull)d << shift);
                sh_cd     = cd;
                if (cd == rr) sh_done = 1;
            }
        }
        __syncthreads();
        if (sh_done || shift == 0) break;

        // ---- next pass scan: histogram + (maybe) compaction, fused ----
        int nshift = shift - 8;
        int nhi    = shift;
        bool do_compact = (!s_compact) && (sh_cd <= 4096);
        if (tid < 256) s_hist[tid] = 0;
        __syncthreads();
        ull pfx = sh_prefix;
        int dom = s_compact ? s_nc : AT;
        for (int base = 0; base < dom; base += 1024) {
            int ci = base + tid;
            bool act = false; int bin = 0; int idx = 0;
            if (ci < dom) {
                idx = s_compact ? (int)s_cand[ci] : ci;
                ull key = key_from(s_conf[idx], idx);
                act = ((key >> nhi) == (pfx >> nhi));
                bin = (int)((key >> nshift) & 255);
            }
            unsigned am = __ballot_sync(0xFFFFFFFFu, act);
            if (act) {
                unsigned peers = __match_any_sync(am, bin);
                if ((__ffs(peers) - 1) == lane)
                    atomicAdd(&s_hist[bin], __popc(peers));
                if (do_compact) {
                    int p = atomicAdd(&s_nc, 1);
                    if (p < 4096) s_cand[p] = (unsigned short)idx;
                }
            }
        }
        __syncthreads();
        if (do_compact) {
            if (tid == 0) s_compact = 1;
            __syncthreads();
        }
    }

    // ---- collect exactly 300 keys >= pivot (SMEM scan; pivot exact) ----
    ull pivot = sh_prefix;
    for (int i = tid; i < AT; i += 1024) {
        ull key = key_from(s_conf[i], i);
        if (key >= pivot) {
            int p = atomicAdd(&s_cnt, 1);
            if (p < MAXDET) s_keys[p] = key;
        }
    }
    __syncthreads();

    // warp-parallel rank-by-counting (keys all distinct)
    for (int k = wid; k < MAXDET; k += 32) {
        ull key = s_keys[k];
        int cnt = 0;
        for (int j = lane; j < MAXDET; j += 32) cnt += (s_keys[j] > key);
#pragma unroll
        for (int o = 16; o > 0; o >>= 1)
            cnt += __shfl_down_sync(0xFFFFFFFFu, cnt, o);
        if (lane == 0) g_topkey[b * MAXDET + cnt] = key;
    }
}

// ---------------------------------------------------------------------------
// K3: DFL decode (thread per (b,box,side)) + fused box assembly on lane s==0.
// ---------------------------------------------------------------------------
__global__ void k_decode(const float* __restrict__ f0,
                         const float* __restrict__ f1,
                         const float* __restrict__ f2) {
    int t = blockIdx.x * blockDim.x + threadIdx.x;   // grid exact: BATCH*300*4
    int b   = t / (MAXDET * 4);
    int r   = t - b * (MAXDET * 4);
    int box = r >> 2, s = r & 3;
    int lane = threadIdx.x & 31;

    ull key = g_topkey[b * MAXDET + box];
    int gidx = (int)(0xFFFFFFFFu - (unsigned)(key & 0xFFFFFFFFull));

    const float* f; int hw, loc, W; float stride;
    if (gidx < A0)           { f = f0; hw = A0; loc = gidx;           W = 80; stride = 8.0f; }
    else if (gidx < A0 + A1) { f = f1; hw = A1; loc = gidx - A0;      W = 40; stride = 16.0f; }
    else                     { f = f2; hw = A2; loc = gidx - A0 - A1; W = 20; stride = 32.0f; }

    const float* p = f + (size_t)b * NO * hw + (size_t)(s * RM) * hw + loc;
    float x[RM];
    float m = -1e30f;
#pragma unroll
    for (int k = 0; k < RM; ++k) {
        x[k] = __ldg(&p[(size_t)k * hw]);
        if (x[k] > m) m = x[k];
    }
    float se = 0.0f, sk = 0.0f;
#pragma unroll
    for (int k = 0; k < RM; ++k) {
        float e = __expf(x[k] - m);
        se += e;
        sk += e * (float)k;
    }
    float d = sk / se;

    int base_lane = lane & ~3;
    float d0 = __shfl_sync(0xFFFFFFFFu, d, base_lane + 0);
    float d1 = __shfl_sync(0xFFFFFFFFu, d, base_lane + 1);
    float d2 = __shfl_sync(0xFFFFFFFFu, d, base_lane + 2);
    float d3 = __shfl_sync(0xFFFFFFFFu, d, base_lane + 3);

    if (s == 0) {
        float conf = __uint_as_float((unsigned)(key >> 32) & 0x7FFFFFFFu);
        float gx = (float)(loc % W) + 0.5f;
        float gy = (float)(loc / W) + 0.5f;
        float x1 = gx - d0, y1 = gy - d1;
        float x2 = gx + d2, y2 = gy + d3;
        float cx = (x1 + x2) * 0.5f * stride;
        float cy = (y1 + y2) * 0.5f * stride;
        float w  = (x2 - x1) * stride;
        float h  = (y2 - y1) * stride;

        float lab = (float)__ldg(&g_label[b * AT + gidx]);
        float off = lab * 10000.0f;
        float bx1 = (cx - w * 0.5f) + off;
        float by1 = (cy - h * 0.5f) + off;
        float bx2 = (cx + w * 0.5f) + off;
        float by2 = (cy + h * 0.5f) + off;
        float aw = bx2 - bx1; if (aw < 0.0f) aw = 0.0f;
        float ah = by2 - by1; if (ah < 0.0f) ah = 0.0f;

        int o = b * MAXDET + box;
        g_bcorn[o] = make_float4(bx1, by1, bx2, by2);
        g_bbox [o] = make_float4(cx, cy, w, h);
        g_bmeta[o] = make_float4(aw * ah, conf, lab, 0.0f);
    }
}

// ---------------------------------------------------------------------------
// K4: class-bucketed sparse adjacency (cross-class IoU is exactly 0 because
// of the 10000*label offset, so only same-class pairs are computed) +
// sparse greedy scan + output. One CTA per batch.
// ---------------------------------------------------------------------------
__global__ void __launch_bounds__(1024, 1)
k_nms(float* __restrict__ out) {
    __shared__ float4 s_c[MAXDET];
    __shared__ float  s_a[MAXDET];
    __shared__ float  s_cf[MAXDET];
    __shared__ int    s_lab[MAXDET];
    __shared__ unsigned s_adj[MAXDET * ADJW];    // 14.4 KB, zeroed
    __shared__ unsigned s_suppw[10];
    __shared__ unsigned s_nz[10];
    __shared__ int s_ccnt[NCLS];     // per-class count
    __shared__ int s_cstart[NCLS];   // per-class exclusive prefix
    __shared__ int s_cpos[NCLS];     // scatter cursor
    __shared__ unsigned short s_items[MAXDET];   // box ids grouped by class

    const int b    = blockIdx.x;
    const int tid  = threadIdx.x;
    const int lane = tid & 31;

    // zero s_adj (3600 words) + bucket state
    for (int t = tid; t < MAXDET * ADJW / 4; t += 1024)
        ((uint4*)s_adj)[t] = make_uint4(0u, 0u, 0u, 0u);
    if (tid < NCLS) s_ccnt[tid] = 0;
    if (tid < 10)   s_nz[tid] = 0u;
    __syncthreads();

    if (tid < MAXDET) {
        s_c[tid]  = g_bcorn[b * MAXDET + tid];
        float4 mt = g_bmeta[b * MAXDET + tid];
        s_a[tid]  = mt.x;
        s_cf[tid] = mt.y;
        int lab = (int)mt.z;
        s_lab[tid] = lab;
        atomicAdd(&s_ccnt[lab], 1);
    }
    __syncthreads();

    // exclusive prefix over 80 classes (single thread; trivial cost)
    if (tid == 0) {
        int acc = 0;
#pragma unroll
        for (int c = 0; c < NCLS; ++c) {
            s_cstart[c] = acc;
            s_cpos[c]   = acc;
            acc += s_ccnt[c];
        }
    }
    __syncthreads();

    if (tid < MAXDET) {
        int p = atomicAdd(&s_cpos[s_lab[tid]], 1);
        s_items[p] = (unsigned short)tid;
    }
    __syncthreads();

    // same-class pair IoU; set adjacency bits (row = smaller index)
    if (tid < MAXDET) {
        int lab   = s_lab[tid];
        int start = s_cstart[lab];
        int cnt   = s_ccnt[lab];
        float4 ci = s_c[tid];
        float  ai = s_a[tid];
        bool any = false;
        for (int t = 0; t < cnt; ++t) {
            int j = (int)s_items[start + t];
            if (j <= tid) continue;
            float4 cj = s_c[j];
            float ix1 = fmaxf(ci.x, cj.x);
            float iy1 = fmaxf(ci.y, cj.y);
            float ix2 = fminf(ci.z, cj.z);
            float iy2 = fminf(ci.w, cj.w);
            float iw = ix2 - ix1; if (iw < 0.0f) iw = 0.0f;
            float ih = iy2 - iy1; if (ih < 0.0f) ih = 0.0f;
            float inter = iw * ih;
            if (inter > 0.0f) {
                float iou = inter / (ai + s_a[j] - inter + 1e-7f);
                if (iou > 0.7f) {
                    atomicOr(&s_adj[tid * ADJW + (j >> 5)], 1u << (j & 31));
                    any = true;
                }
            }
        }
        if (any) atomicOr(&s_nz[tid >> 5], 1u << (tid & 31));
    }

    // validity (supp-at-start) bitmask (warps 0..9, full-warp ballots)
    if (tid < 320) {
        bool sup0 = (tid < MAXDET) ? !(s_cf[tid] > 0.001f) : false;
        unsigned wv = __ballot_sync(0xFFFFFFFFu, sup0);
        if (lane == 0) s_suppw[tid >> 5] = wv;
    }
    __syncthreads();

    // sparse greedy scan: rows with nonzero adjacency only; ascending order;
    // a row's OR only sets bits j>i, so re-masking rem preserves greedy order.
    if (tid == 0) {
        unsigned supp[10];
#pragma unroll
        for (int k = 0; k < 10; ++k) supp[k] = s_suppw[k];
#pragma unroll
        for (int w = 0; w < 10; ++w) {
            unsigned rem = s_nz[w] & ~supp[w];
            while (rem) {
                int bit = __ffs(rem) - 1;
                const uint4* r4 = (const uint4*)&s_adj[((w << 5) + bit) * ADJW];
                uint4 ra = r4[0], rb = r4[1], rc = r4[2];
                supp[0] |= ra.x; supp[1] |= ra.y; supp[2] |= ra.z; supp[3] |= ra.w;
                supp[4] |= rb.x; supp[5] |= rb.y; supp[6] |= rb.z; supp[7] |= rb.w;
                supp[8] |= rc.x; supp[9] |= rc.y;
                rem &= ~(1u << bit);
                rem &= ~supp[w];
            }
        }
#pragma unroll
        for (int k = 0; k < 10; ++k) s_suppw[k] = supp[k];
    }
    __syncthreads();

    if (tid < MAXDET) {
        bool sup = (s_suppw[tid >> 5] >> (tid & 31)) & 1u;
        float4 bb = g_bbox[b * MAXDET + tid];
        float4 mt = g_bmeta[b * MAXDET + tid];
        float conf = sup ? 0.0f : mt.y;
        float* o = out + ((size_t)b * MAXDET + tid) * 6;
        o[0] = bb.x; o[1] = bb.y; o[2] = bb.z; o[3] = bb.w;
        o[4] = conf; o[5] = mt.z;
    }
}

extern "C" void kernel_launch(void* const* d_in, const int* in_sizes, int n_in,
                              void* d_out, int out_size) {
    const float* f0 = (const float*)d_in[0];
    const float* f1 = (const float*)d_in[1];
    const float* f2 = (const float*)d_in[2];
    float* out = (float*)d_out;

    dim3 g1((AT / 4 + 255) / 256, BATCH);
    k_conf<<<g1, 256>>>(f0, f1, f2);
    k_topk<<<BATCH, 1024>>>();
    k_decode<<<BATCH * MAXDET * 4 / 256, 256>>>(f0, f1, f2);
    k_nms<<<BATCH, 1024>>>(out);
}

// round 12
// speedup vs baseline: 1.4996x; 1.0460x over previous
#include <cuda_runtime.h>

#define BATCH   64
#define NCLS    80
#define RM      16
#define NO      144      // 80 + 4*16
#define A0      6400     // 80x80
#define A1      1600     // 40x40
#define A2      400      // 20x20
#define AT      8400
#define MAXDET  300
#define ADJW    12       // padded words per adjacency row (10 used)

typedef unsigned long long ull;

__device__ float g_conf[BATCH * AT];
__device__ int   g_label[BATCH * AT];

// ---------------------------------------------------------------------------
// K1: per-anchor class argmax + sigmoid(max), float4-vectorized.
// ---------------------------------------------------------------------------
__global__ void k_conf(const float* __restrict__ f0,
                       const float* __restrict__ f1,
                       const float* __restrict__ f2) {
    int q = blockIdx.x * blockDim.x + threadIdx.x;
    int b = blockIdx.y;
    if (q >= AT / 4) return;
    int a = q * 4;

    const float* f; int hw, loc;
    if (a < A0)            { f = f0; hw = A0; loc = a; }
    else if (a < A0 + A1)  { f = f1; hw = A1; loc = a - A0; }
    else                   { f = f2; hw = A2; loc = a - A0 - A1; }

    const float4* base = (const float4*)(f + ((size_t)b * NO + 4 * RM) * hw) + (loc >> 2);
    int hw4 = hw >> 2;

    float4 v = base[0];
    float m0 = v.x, m1 = v.y, m2 = v.z, m3 = v.w;
    int l0 = 0, l1 = 0, l2 = 0, l3 = 0;
#pragma unroll 8
    for (int c = 1; c < NCLS; ++c) {
        v = base[(size_t)c * hw4];
        if (v.x > m0) { m0 = v.x; l0 = c; }
        if (v.y > m1) { m1 = v.y; l1 = c; }
        if (v.z > m2) { m2 = v.z; l2 = c; }
        if (v.w > m3) { m3 = v.w; l3 = c; }
    }
    float4 cf;
    cf.x = 1.0f / (1.0f + __expf(-m0));
    cf.y = 1.0f / (1.0f + __expf(-m1));
    cf.z = 1.0f / (1.0f + __expf(-m2));
    cf.w = 1.0f / (1.0f + __expf(-m3));
    *(float4*)&g_conf[b * AT + a] = cf;
    int4 lb; lb.x = l0; lb.y = l1; lb.z = l2; lb.w = l3;
    *(int4*)&g_label[b * AT + a] = lb;
}

// key = (monotonic conf bits << 32) | (~index); conf>0 so mono map = |signbit.
__device__ __forceinline__ ull key_from(float c, int i) {
    unsigned ub = __float_as_uint(c) | 0x80000000u;
    return ((ull)ub << 32) | (ull)(0xFFFFFFFFu - (unsigned)i);
}

// ---------------------------------------------------------------------------
// K2 (fused): per-batch top-300 radix select -> DFL decode -> class-bucketed
// NMS -> output. One CTA per batch. The 33.6KB conf buffer is dead after key
// collection and is overlaid by all decode/NMS arrays.
// ---------------------------------------------------------------------------
__global__ void __launch_bounds__(1024, 1)
k_post(const float* __restrict__ f0,
       const float* __restrict__ f1,
       const float* __restrict__ f2,
       float* __restrict__ out) {
    __shared__ __align__(16) char s_buf[33600];
    __shared__ unsigned short s_cand[4096];
    __shared__ int  s_hist[256];
    __shared__ ull  s_keys[MAXDET];
    __shared__ ull  s_skey[MAXDET];
    __shared__ ull  sh_prefix;
    __shared__ int  sh_rank, sh_done, sh_cd;
    __shared__ int  s_cnt, s_nc, s_compact;
    __shared__ unsigned s_suppw[10];
    __shared__ unsigned s_nz[10];

    // overlay pointers (active only after top-k collection completes)
    unsigned*       s_adj   = (unsigned*)s_buf;                    // 14400 B
    float4*         s_c     = (float4*)(s_buf + 14400);            //  4800 B
    float*          s_d4    = (float*)(s_buf + 19200);             //  4800 B
    float*          s_a     = (float*)(s_buf + 24000);             //  1200 B
    float*          s_cf    = (float*)(s_buf + 25200);             //  1200 B
    int*            s_lab   = (int*)(s_buf + 26400);               //  1200 B
    unsigned short* s_items = (unsigned short*)(s_buf + 27600);    //   600 B
    int*            s_ccnt  = (int*)(s_buf + 28200);               //   320 B
    int*            s_cstart= (int*)(s_buf + 28520);               //   320 B
    int*            s_cpos  = (int*)(s_buf + 28840);               //   320 B
    float*          s_conf  = (float*)s_buf;                       // topk view

    const int b    = blockIdx.x;
    const int tid  = threadIdx.x;
    const int lane = tid & 31;
    const int wid  = tid >> 5;

    if (tid == 0) {
        sh_prefix = 0ull; sh_rank = MAXDET; sh_done = 0; sh_cd = AT;
        s_cnt = 0; s_nc = 0; s_compact = 0;
    }
    if (tid < 256) s_hist[tid] = 0;
    __syncthreads();

    // ==== Phase 1: top-300 radix select (proven code) ====
    for (int base = 0; base < AT; base += 1024) {
        int i = base + tid;
        bool in = (i < AT);
        float c = 0.0f;
        int bin = 0;
        if (in) {
            c = g_conf[b * AT + i];
            s_conf[i] = c;
            bin = (int)((__float_as_uint(c) | 0x80000000u) >> 24);
        }
        unsigned am = __ballot_sync(0xFFFFFFFFu, in);
        if (in) {
            unsigned peers = __match_any_sync(am, bin);
            if ((__ffs(peers) - 1) == lane)
                atomicAdd(&s_hist[bin], __popc(peers));
        }
    }
    __syncthreads();

    for (int shift = 56; shift >= 0; shift -= 8) {
        if (wid == 0) {
            int base = 255 - lane * 8;
            int loc[8]; int gs = 0;
#pragma unroll
            for (int t = 0; t < 8; ++t) { loc[t] = s_hist[base - t]; gs += loc[t]; }
            int cum = gs;
#pragma unroll
            for (int o = 1; o < 32; o <<= 1) {
                int v = __shfl_up_sync(0xFFFFFFFFu, cum, o);
                if (lane >= o) cum += v;
            }
            int r = sh_rank;
            bool found = (cum >= r) && ((cum - gs) < r);
            unsigned m = __ballot_sync(0xFFFFFFFFu, found);
            int src = __ffs(m) - 1;
            if (lane == src) {
                int c = cum - gs;
                int d = base, rr = r, cd = 0;
#pragma unroll
                for (int t = 0; t < 8; ++t) {
                    c += loc[t];
                    if (c >= r) { d = base - t; cd = loc[t]; rr = r - (c - loc[t]); break; }
                }
                sh_rank   = rr;
                sh_prefix = sh_prefix | ((ull)d << shift);
                sh_cd     = cd;
                if (cd == rr) sh_done = 1;
            }
        }
        __syncthreads();
        if (sh_done || shift == 0) break;

        int nshift = shift - 8;
        int nhi    = shift;
        bool do_compact = (!s_compact) && (sh_cd <= 4096);
        if (tid < 256) s_hist[tid] = 0;
        __syncthreads();
        ull pfx = sh_prefix;
        int dom = s_compact ? s_nc : AT;
        for (int base = 0; base < dom; base += 1024) {
            int ci = base + tid;
            bool act = false; int bin = 0; int idx = 0;
            if (ci < dom) {
                idx = s_compact ? (int)s_cand[ci] : ci;
                ull key = key_from(s_conf[idx], idx);
                act = ((key >> nhi) == (pfx >> nhi));
                bin = (int)((key >> nshift) & 255);
            }
            unsigned am = __ballot_sync(0xFFFFFFFFu, act);
            if (act) {
                unsigned peers = __match_any_sync(am, bin);
                if ((__ffs(peers) - 1) == lane)
                    atomicAdd(&s_hist[bin], __popc(peers));
                if (do_compact) {
                    int p = atomicAdd(&s_nc, 1);
                    if (p < 4096) s_cand[p] = (unsigned short)idx;
                }
            }
        }
        __syncthreads();
        if (do_compact) {
            if (tid == 0) s_compact = 1;
            __syncthreads();
        }
    }

    // collect exactly 300 keys >= pivot
    ull pivot = sh_prefix;
    for (int i = tid; i < AT; i += 1024) {
        ull key = key_from(s_conf[i], i);
        if (key >= pivot) {
            int p = atomicAdd(&s_cnt, 1);
            if (p < MAXDET) s_keys[p] = key;
        }
    }
    __syncthreads();

    // warp-parallel rank-by-counting -> sorted keys in SMEM
    for (int k = wid; k < MAXDET; k += 32) {
        ull key = s_keys[k];
        int cnt = 0;
        for (int j = lane; j < MAXDET; j += 32) cnt += (s_keys[j] > key);
#pragma unroll
        for (int o = 16; o > 0; o >>= 1)
            cnt += __shfl_down_sync(0xFFFFFFFFu, cnt, o);
        if (lane == 0) s_skey[cnt] = key;
    }
    __syncthreads();
    // ---- s_conf is dead from here; overlay becomes active ----

    // ==== Phase 2: DFL decode, 1200 (box,side) tasks ====
    for (int t = tid; t < MAXDET * 4; t += 1024) {
        int box = t >> 2, s = t & 3;
        ull key = s_skey[box];
        int gidx = (int)(0xFFFFFFFFu - (unsigned)(key & 0xFFFFFFFFull));

        const float* f; int hw, loc;
        if (gidx < A0)           { f = f0; hw = A0; loc = gidx; }
        else if (gidx < A0 + A1) { f = f1; hw = A1; loc = gidx - A0; }
        else                     { f = f2; hw = A2; loc = gidx - A0 - A1; }

        const float* p = f + (size_t)b * NO * hw + (size_t)(s * RM) * hw + loc;
        float x[RM];
        float m = -1e30f;
#pragma unroll
        for (int k = 0; k < RM; ++k) {
            x[k] = __ldg(&p[(size_t)k * hw]);
            if (x[k] > m) m = x[k];
        }
        float se = 0.0f, sk = 0.0f;
#pragma unroll
        for (int k = 0; k < RM; ++k) {
            float e = __expf(x[k] - m);
            se += e;
            sk += e * (float)k;
        }
        s_d4[t] = sk / se;     // t == box*4 + s
    }
    __syncthreads();

    // ==== Phase 3: zero NMS state + box setup ====
    for (int t = tid; t < (MAXDET * ADJW) / 4; t += 1024)
        ((uint4*)s_adj)[t] = make_uint4(0u, 0u, 0u, 0u);
    if (tid < NCLS) s_ccnt[tid] = 0;
    if (tid < 10)   s_nz[tid]  = 0u;

    if (tid < MAXDET) {
        ull key = s_skey[tid];
        int gidx = (int)(0xFFFFFFFFu - (unsigned)(key & 0xFFFFFFFFull));
        float conf = __uint_as_float((unsigned)(key >> 32) & 0x7FFFFFFFu);

        int loc, W; float stride;
        if (gidx < A0)           { loc = gidx;           W = 80; stride = 8.0f; }
        else if (gidx < A0 + A1) { loc = gidx - A0;      W = 40; stride = 16.0f; }
        else                     { loc = gidx - A0 - A1; W = 20; stride = 32.0f; }

        float d0 = s_d4[tid * 4 + 0];
        float d1 = s_d4[tid * 4 + 1];
        float d2 = s_d4[tid * 4 + 2];
        float d3 = s_d4[tid * 4 + 3];

        float gx = (float)(loc % W) + 0.5f;
        float gy = (float)(loc / W) + 0.5f;
        float x1 = gx - d0, y1 = gy - d1;
        float x2 = gx + d2, y2 = gy + d3;
        float cx = (x1 + x2) * 0.5f * stride;
        float cy = (y1 + y2) * 0.5f * stride;
        float w  = (x2 - x1) * stride;
        float h  = (y2 - y1) * stride;

        int lab = __ldg(&g_label[b * AT + gidx]);
        float off = (float)lab * 10000.0f;
        float bx1 = (cx - w * 0.5f) + off;
        float by1 = (cy - h * 0.5f) + off;
        float bx2 = (cx + w * 0.5f) + off;
        float by2 = (cy + h * 0.5f) + off;
        float aw = bx2 - bx1; if (aw < 0.0f) aw = 0.0f;
        float ah = by2 - by1; if (ah < 0.0f) ah = 0.0f;

        s_c[tid]   = make_float4(bx1, by1, bx2, by2);
        s_a[tid]   = aw * ah;
        s_cf[tid]  = conf;
        s_lab[tid] = lab;
        // reuse s_d4 row as the output cxcywh (same thread owns the row)
        s_d4[tid * 4 + 0] = cx;
        s_d4[tid * 4 + 1] = cy;
        s_d4[tid * 4 + 2] = w;
        s_d4[tid * 4 + 3] = h;
    }
    __syncthreads();

    // ==== Phase 4: class bucketing ====
    if (tid < MAXDET) atomicAdd(&s_ccnt[s_lab[tid]], 1);
    __syncthreads();
    if (tid == 0) {
        int acc = 0;
#pragma unroll
        for (int c = 0; c < NCLS; ++c) {
            s_cstart[c] = acc;
            s_cpos[c]   = acc;
            acc += s_ccnt[c];
        }
    }
    __syncthreads();
    if (tid < MAXDET) {
        int p = atomicAdd(&s_cpos[s_lab[tid]], 1);
        s_items[p] = (unsigned short)tid;
    }
    __syncthreads();

    // ==== Phase 5: same-class adjacency (cross-class IoU is exactly 0) ====
    if (tid < MAXDET) {
        int lab   = s_lab[tid];
        int start = s_cstart[lab];
        int cnt   = s_ccnt[lab];
        float4 ci = s_c[tid];
        float  ai = s_a[tid];
        bool any = false;
        for (int t = 0; t < cnt; ++t) {
            int j = (int)s_items[start + t];
            if (j <= tid) continue;
            float4 cj = s_c[j];
            float ix1 = fmaxf(ci.x, cj.x);
            float iy1 = fmaxf(ci.y, cj.y);
            float ix2 = fminf(ci.z, cj.z);
            float iy2 = fminf(ci.w, cj.w);
            float iw = ix2 - ix1; if (iw < 0.0f) iw = 0.0f;
            float ih = iy2 - iy1; if (ih < 0.0f) ih = 0.0f;
            float inter = iw * ih;
            if (inter > 0.0f) {
                float iou = inter / (ai + s_a[j] - inter + 1e-7f);
                if (iou > 0.7f) {
                    atomicOr(&s_adj[tid * ADJW + (j >> 5)], 1u << (j & 31));
                    any = true;
                }
            }
        }
        if (any) atomicOr(&s_nz[tid >> 5], 1u << (tid & 31));
    }

    // validity (supp-at-start) bitmask
    if (tid < 320) {
        bool sup0 = (tid < MAXDET) ? !(s_cf[tid] > 0.001f) : false;
        unsigned wv = __ballot_sync(0xFFFFFFFFu, sup0);
        if (lane == 0) s_suppw[tid >> 5] = wv;
    }
    __syncthreads();

    // ==== Phase 6: sparse greedy scan ====
    if (tid == 0) {
        unsigned supp[10];
#pragma unroll
        for (int k = 0; k < 10; ++k) supp[k] = s_suppw[k];
#pragma unroll
        for (int w = 0; w < 10; ++w) {
            unsigned rem = s_nz[w] & ~supp[w];
            while (rem) {
                int bit = __ffs(rem) - 1;
                const uint4* r4 = (const uint4*)&s_adj[((w << 5) + bit) * ADJW];
                uint4 ra = r4[0], rb = r4[1], rc = r4[2];
                supp[0] |= ra.x; supp[1] |= ra.y; supp[2] |= ra.z; supp[3] |= ra.w;
                supp[4] |= rb.x; supp[5] |= rb.y; supp[6] |= rb.z; supp[7] |= rb.w;
                supp[8] |= rc.x; supp[9] |= rc.y;
                rem &= ~(1u << bit);
                rem &= ~supp[w];
            }
        }
#pragma unroll
        for (int k = 0; k < 10; ++k) s_suppw[k] = supp[k];
    }
    __syncthreads();

    // ==== Phase 7: output (300, 6) rows ====
    if (tid < MAXDET) {
        bool sup = (s_suppw[tid >> 5] >> (tid & 31)) & 1u;
        float conf = sup ? 0.0f : s_cf[tid];
        float* o = out + ((size_t)b * MAXDET + tid) * 6;
        o[0] = s_d4[tid * 4 + 0];
        o[1] = s_d4[tid * 4 + 1];
        o[2] = s_d4[tid * 4 + 2];
        o[3] = s_d4[tid * 4 + 3];
        o[4] = conf;
        o[5] = (float)s_lab[tid];
    }
}

extern "C" void kernel_launch(void* const* d_in, const int* in_sizes, int n_in,
                              void* d_out, int out_size) {
    const float* f0 = (const float*)d_in[0];
    const float* f1 = (const float*)d_in[1];
    const float* f2 = (const float*)d_in[2];
    float* out = (float*)d_out;

    dim3 g1((AT / 4 + 255) / 256, BATCH);
    k_conf<<<g1, 256>>>(f0, f1, f2);
    k_post<<<BATCH, 1024>>>(f0, f1, f2, out);
}

// round 13
// speedup vs baseline: 1.5926x; 1.0620x over previous
#include <cuda_runtime.h>

#define BATCH   64
#define NCLS    80
#define RM      16
#define NO      144      // 80 + 4*16
#define A0      6400     // 80x80
#define A1      1600     // 40x40
#define A2      400      // 20x20
#define AT      8400
#define MAXDET  300
#define ADJW    12       // padded words per adjacency row (10 used)

typedef unsigned long long ull;

__device__ float g_conf[BATCH * AT];
__device__ int   g_label[BATCH * AT];

// ---------------------------------------------------------------------------
// K1: per-anchor class argmax + sigmoid(max), float4-vectorized.
// ---------------------------------------------------------------------------
__global__ void k_conf(const float* __restrict__ f0,
                       const float* __restrict__ f1,
                       const float* __restrict__ f2) {
    int q = blockIdx.x * blockDim.x + threadIdx.x;
    int b = blockIdx.y;
    if (q >= AT / 4) return;
    int a = q * 4;

    const float* f; int hw, loc;
    if (a < A0)            { f = f0; hw = A0; loc = a; }
    else if (a < A0 + A1)  { f = f1; hw = A1; loc = a - A0; }
    else                   { f = f2; hw = A2; loc = a - A0 - A1; }

    const float4* base = (const float4*)(f + ((size_t)b * NO + 4 * RM) * hw) + (loc >> 2);
    int hw4 = hw >> 2;

    float4 v = base[0];
    float m0 = v.x, m1 = v.y, m2 = v.z, m3 = v.w;
    int l0 = 0, l1 = 0, l2 = 0, l3 = 0;
#pragma unroll 8
    for (int c = 1; c < NCLS; ++c) {
        v = base[(size_t)c * hw4];
        if (v.x > m0) { m0 = v.x; l0 = c; }
        if (v.y > m1) { m1 = v.y; l1 = c; }
        if (v.z > m2) { m2 = v.z; l2 = c; }
        if (v.w > m3) { m3 = v.w; l3 = c; }
    }
    float4 cf;
    cf.x = 1.0f / (1.0f + __expf(-m0));
    cf.y = 1.0f / (1.0f + __expf(-m1));
    cf.z = 1.0f / (1.0f + __expf(-m2));
    cf.w = 1.0f / (1.0f + __expf(-m3));
    *(float4*)&g_conf[b * AT + a] = cf;
    int4 lb; lb.x = l0; lb.y = l1; lb.z = l2; lb.w = l3;
    *(int4*)&g_label[b * AT + a] = lb;
}

// key = (monotonic conf bits << 32) | (~index); conf>0 so mono map = |signbit.
__device__ __forceinline__ ull key_from(float c, int i) {
    unsigned ub = __float_as_uint(c) | 0x80000000u;
    return ((ull)ub << 32) | (ull)(0xFFFFFFFFu - (unsigned)i);
}

// ---------------------------------------------------------------------------
// K2 (fused): per-batch top-300 radix select with direct-rank early finish ->
// DFL decode -> class-bucketed NMS -> output. One CTA per batch. The 33.6KB
// conf buffer is dead after key collection and is overlaid by decode/NMS
// arrays.
// ---------------------------------------------------------------------------
__global__ void __launch_bounds__(1024, 1)
k_post(const float* __restrict__ f0,
       const float* __restrict__ f1,
       const float* __restrict__ f2,
       float* __restrict__ out) {
    __shared__ __align__(16) char s_buf[33600];
    __shared__ ull  s_dkeys[512];        // direct-rank candidate keys
    __shared__ int  s_hist[256];
    __shared__ ull  s_keys[MAXDET];
    __shared__ ull  s_skey[MAXDET];
    __shared__ ull  sh_prefix;
    __shared__ int  sh_rank, sh_done, sh_cd;
    __shared__ int  s_cnt, s_nc;
    __shared__ unsigned s_suppw[10];
    __shared__ unsigned s_nz[10];

    // overlay pointers (active only after top-k collection completes)
    unsigned*       s_adj   = (unsigned*)s_buf;                    // 14400 B
    float4*         s_c     = (float4*)(s_buf + 14400);            //  4800 B
    float*          s_d4    = (float*)(s_buf + 19200);             //  4800 B
    float*          s_a     = (float*)(s_buf + 24000);             //  1200 B
    float*          s_cf    = (float*)(s_buf + 25200);             //  1200 B
    int*            s_lab   = (int*)(s_buf + 26400);               //  1200 B
    unsigned short* s_items = (unsigned short*)(s_buf + 27600);    //   600 B
    int*            s_ccnt  = (int*)(s_buf + 28200);               //   320 B
    int*            s_cstart= (int*)(s_buf + 28520);               //   320 B
    int*            s_cpos  = (int*)(s_buf + 28840);               //   320 B
    float*          s_conf  = (float*)s_buf;                       // topk view

    const int b    = blockIdx.x;
    const int tid  = threadIdx.x;
    const int lane = tid & 31;
    const int wid  = tid >> 5;

    if (tid == 0) {
        sh_prefix = 0ull; sh_rank = MAXDET; sh_done = 0; sh_cd = AT;
        s_cnt = 0; s_nc = 0;
    }
    if (tid < 256) s_hist[tid] = 0;
    __syncthreads();

    // ==== Phase 1: top-300 selection ====
    // pass 1 (byte [56,64)): copy global->SMEM fused with histogram
    for (int base = 0; base < AT; base += 1024) {
        int i = base + tid;
        bool in = (i < AT);
        float c = 0.0f;
        int bin = 0;
        if (in) {
            c = g_conf[b * AT + i];
            s_conf[i] = c;
            bin = (int)((__float_as_uint(c) | 0x80000000u) >> 24);
        }
        unsigned am = __ballot_sync(0xFFFFFFFFu, in);
        if (in) {
            unsigned peers = __match_any_sync(am, bin);
            if ((__ffs(peers) - 1) == lane)
                atomicAdd(&s_hist[bin], __popc(peers));
        }
    }
    __syncthreads();

    for (int shift = 56; ; shift -= 8) {
        // digit selection from s_hist for byte [shift, shift+8) (warp 0)
        if (wid == 0) {
            int base = 255 - lane * 8;
            int loc[8]; int gs = 0;
#pragma unroll
            for (int t = 0; t < 8; ++t) { loc[t] = s_hist[base - t]; gs += loc[t]; }
            int cum = gs;
#pragma unroll
            for (int o = 1; o < 32; o <<= 1) {
                int v = __shfl_up_sync(0xFFFFFFFFu, cum, o);
                if (lane >= o) cum += v;
            }
            int r = sh_rank;
            bool found = (cum >= r) && ((cum - gs) < r);
            unsigned m = __ballot_sync(0xFFFFFFFFu, found);
            int src = __ffs(m) - 1;
            if (lane == src) {
                int c = cum - gs;
                int d = base, rr = r, cd = 0;
#pragma unroll
                for (int t = 0; t < 8; ++t) {
                    c += loc[t];
                    if (c >= r) { d = base - t; cd = loc[t]; rr = r - (c - loc[t]); break; }
                }
                sh_rank   = rr;
                sh_prefix = sh_prefix | ((ull)d << shift);
                sh_cd     = cd;
                if (cd == rr) sh_done = 1;   // whole bin selected: prefix exact
            }
        }
        __syncthreads();
        if (sh_done || shift == 0) break;

        if (sh_cd <= 512) {
            // direct finish: compact actives (prefix bits [shift,64) match),
            // then exact rank-by-counting; rank rr-1 key IS the 64-bit pivot.
            if (tid == 0) s_nc = 0;
            __syncthreads();
            ull pfx = sh_prefix;
            for (int i = tid; i < AT; i += 1024) {
                ull key = key_from(s_conf[i], i);
                if ((key >> shift) == (pfx >> shift)) {
                    int p = atomicAdd(&s_nc, 1);
                    if (p < 512) s_dkeys[p] = key;
                }
            }
            __syncthreads();
            int cd = s_nc;
            int r  = sh_rank;
            if (tid < cd) {
                ull mine = s_dkeys[tid];
                int cnt = 0;
                for (int j = 0; j < cd; ++j) cnt += (s_dkeys[j] > mine);
                if (cnt == r - 1) sh_prefix = mine;   // exact pivot
            }
            __syncthreads();
            break;
        }

        // another radix pass: histogram byte [shift-8, shift) among actives
        int nshift = shift - 8;
        if (tid < 256) s_hist[tid] = 0;
        __syncthreads();
        ull pfx = sh_prefix;
        for (int base = 0; base < AT; base += 1024) {
            int i = base + tid;
            bool act = false; int bin = 0;
            if (i < AT) {
                ull key = key_from(s_conf[i], i);
                act = ((key >> shift) == (pfx >> shift));
                bin = (int)((key >> nshift) & 255);
            }
            unsigned am = __ballot_sync(0xFFFFFFFFu, act);
            if (act) {
                unsigned peers = __match_any_sync(am, bin);
                if ((__ffs(peers) - 1) == lane)
                    atomicAdd(&s_hist[bin], __popc(peers));
            }
        }
        __syncthreads();
    }

    // collect exactly 300 keys >= pivot
    ull pivot = sh_prefix;
    for (int i = tid; i < AT; i += 1024) {
        ull key = key_from(s_conf[i], i);
        if (key >= pivot) {
            int p = atomicAdd(&s_cnt, 1);
            if (p < MAXDET) s_keys[p] = key;
        }
    }
    __syncthreads();

    // warp-parallel rank-by-counting -> sorted keys in SMEM
    for (int k = wid; k < MAXDET; k += 32) {
        ull key = s_keys[k];
        int cnt = 0;
        for (int j = lane; j < MAXDET; j += 32) cnt += (s_keys[j] > key);
#pragma unroll
        for (int o = 16; o > 0; o >>= 1)
            cnt += __shfl_down_sync(0xFFFFFFFFu, cnt, o);
        if (lane == 0) s_skey[cnt] = key;
    }
    __syncthreads();
    // ---- s_conf is dead from here; overlay becomes active ----

    // ==== Phase 2: DFL decode, 1200 (box,side) tasks ====
    // softmax without max-subtraction: scale-invariant, |x| small; lets exp
    // pipeline with the gathers instead of waiting on a 16-deep max chain.
    for (int t = tid; t < MAXDET * 4; t += 1024) {
        int box = t >> 2, s = t & 3;
        ull key = s_skey[box];
        int gidx = (int)(0xFFFFFFFFu - (unsigned)(key & 0xFFFFFFFFull));

        const float* f; int hw, loc;
        if (gidx < A0)           { f = f0; hw = A0; loc = gidx; }
        else if (gidx < A0 + A1) { f = f1; hw = A1; loc = gidx - A0; }
        else                     { f = f2; hw = A2; loc = gidx - A0 - A1; }

        const float* p = f + (size_t)b * NO * hw + (size_t)(s * RM) * hw + loc;
        float se = 0.0f, sk = 0.0f;
#pragma unroll
        for (int k = 0; k < RM; ++k) {
            float e = __expf(__ldg(&p[(size_t)k * hw]));
            se += e;
            sk += e * (float)k;
        }
        s_d4[t] = sk / se;     // t == box*4 + s
    }
    __syncthreads();

    // ==== Phase 3: zero NMS state + box setup ====
    for (int t = tid; t < (MAXDET * ADJW) / 4; t += 1024)
        ((uint4*)s_adj)[t] = make_uint4(0u, 0u, 0u, 0u);
    if (tid < NCLS) s_ccnt[tid] = 0;
    if (tid < 10)   s_nz[tid]  = 0u;

    if (tid < MAXDET) {
        ull key = s_skey[tid];
        int gidx = (int)(0xFFFFFFFFu - (unsigned)(key & 0xFFFFFFFFull));
        float conf = __uint_as_float((unsigned)(key >> 32) & 0x7FFFFFFFu);

        int loc, W; float stride;
        if (gidx < A0)           { loc = gidx;           W = 80; stride = 8.0f; }
        else if (gidx < A0 + A1) { loc = gidx - A0;      W = 40; stride = 16.0f; }
        else                     { loc = gidx - A0 - A1; W = 20; stride = 32.0f; }

        float d0 = s_d4[tid * 4 + 0];
        float d1 = s_d4[tid * 4 + 1];
        float d2 = s_d4[tid * 4 + 2];
        float d3 = s_d4[tid * 4 + 3];

        float gx = (float)(loc % W) + 0.5f;
        float gy = (float)(loc / W) + 0.5f;
        float x1 = gx - d0, y1 = gy - d1;
        float x2 = gx + d2, y2 = gy + d3;
        float cx = (x1 + x2) * 0.5f * stride;
        float cy = (y1 + y2) * 0.5f * stride;
        float w  = (x2 - x1) * stride;
        float h  = (y2 - y1) * stride;

        int lab = __ldg(&g_label[b * AT + gidx]);
        float off = (float)lab * 10000.0f;
        float bx1 = (cx - w * 0.5f) + off;
        float by1 = (cy - h * 0.5f) + off;
        float bx2 = (cx + w * 0.5f) + off;
        float by2 = (cy + h * 0.5f) + off;
        float aw = bx2 - bx1; if (aw < 0.0f) aw = 0.0f;
        float ah = by2 - by1; if (ah < 0.0f) ah = 0.0f;

        s_c[tid]   = make_float4(bx1, by1, bx2, by2);
        s_a[tid]   = aw * ah;
        s_cf[tid]  = conf;
        s_lab[tid] = lab;
        // reuse s_d4 row as the output cxcywh (same thread owns the row)
        s_d4[tid * 4 + 0] = cx;
        s_d4[tid * 4 + 1] = cy;
        s_d4[tid * 4 + 2] = w;
        s_d4[tid * 4 + 3] = h;
    }
    __syncthreads();

    // ==== Phase 4: class bucketing ====
    if (tid < MAXDET) atomicAdd(&s_ccnt[s_lab[tid]], 1);
    __syncthreads();
    if (tid == 0) {
        int acc = 0;
#pragma unroll
        for (int c = 0; c < NCLS; ++c) {
            s_cstart[c] = acc;
            s_cpos[c]   = acc;
            acc += s_ccnt[c];
        }
    }
    __syncthreads();
    if (tid < MAXDET) {
        int p = atomicAdd(&s_cpos[s_lab[tid]], 1);
        s_items[p] = (unsigned short)tid;
    }
    __syncthreads();

    // ==== Phase 5: same-class adjacency (cross-class IoU is exactly 0) ====
    if (tid < MAXDET) {
        int lab   = s_lab[tid];
        int start = s_cstart[lab];
        int cnt   = s_ccnt[lab];
        float4 ci = s_c[tid];
        float  ai = s_a[tid];
        bool any = false;
        for (int t = 0; t < cnt; ++t) {
            int j = (int)s_items[start + t];
            if (j <= tid) continue;
            float4 cj = s_c[j];
            float ix1 = fmaxf(ci.x, cj.x);
            float iy1 = fmaxf(ci.y, cj.y);
            float ix2 = fminf(ci.z, cj.z);
            float iy2 = fminf(ci.w, cj.w);
            float iw = ix2 - ix1; if (iw < 0.0f) iw = 0.0f;
            float ih = iy2 - iy1; if (ih < 0.0f) ih = 0.0f;
            float inter = iw * ih;
            if (inter > 0.0f) {
                float iou = inter / (ai + s_a[j] - inter + 1e-7f);
                if (iou > 0.7f) {
                    atomicOr(&s_adj[tid * ADJW + (j >> 5)], 1u << (j & 31));
                    any = true;
                }
            }
        }
        if (any) atomicOr(&s_nz[tid >> 5], 1u << (tid & 31));
    }

    // validity (supp-at-start) bitmask
    if (tid < 320) {
        bool sup0 = (tid < MAXDET) ? !(s_cf[tid] > 0.001f) : false;
        unsigned wv = __ballot_sync(0xFFFFFFFFu, sup0);
        if (lane == 0) s_suppw[tid >> 5] = wv;
    }
    __syncthreads();

    // ==== Phase 6: sparse greedy scan ====
    if (tid == 0) {
        unsigned supp[10];
#pragma unroll
        for (int k = 0; k < 10; ++k) supp[k] = s_suppw[k];
#pragma unroll
        for (int w = 0; w < 10; ++w) {
            unsigned rem = s_nz[w] & ~supp[w];
            while (rem) {
                int bit = __ffs(rem) - 1;
                const uint4* r4 = (const uint4*)&s_adj[((w << 5) + bit) * ADJW];
                uint4 ra = r4[0], rb = r4[1], rc = r4[2];
                supp[0] |= ra.x; supp[1] |= ra.y; supp[2] |= ra.z; supp[3] |= ra.w;
                supp[4] |= rb.x; supp[5] |= rb.y; supp[6] |= rb.z; supp[7] |= rb.w;
                supp[8] |= rc.x; supp[9] |= rc.y;
                rem &= ~(1u << bit);
                rem &= ~supp[w];
            }
        }
#pragma unroll
        for (int k = 0; k < 10; ++k) s_suppw[k] = supp[k];
    }
    __syncthreads();

    // ==== Phase 7: output (300, 6) rows ====
    if (tid < MAXDET) {
        bool sup = (s_suppw[tid >> 5] >> (tid & 31)) & 1u;
        float conf = sup ? 0.0f : s_cf[tid];
        float* o = out + ((size_t)b * MAXDET + tid) * 6;
        o[0] = s_d4[tid * 4 + 0];
        o[1] = s_d4[tid * 4 + 1];
        o[2] = s_d4[tid * 4 + 2];
        o[3] = s_d4[tid * 4 + 3];
        o[4] = conf;
        o[5] = (float)s_lab[tid];
    }
}

extern "C" void kernel_launch(void* const* d_in, const int* in_sizes, int n_in,
                              void* d_out, int out_size) {
    const float* f0 = (const float*)d_in[0];
    const float* f1 = (const float*)d_in[1];
    const float* f2 = (const float*)d_in[2];
    float* out = (float*)d_out;

    dim3 g1((AT / 4 + 255) / 256, BATCH);
    k_conf<<<g1, 256>>>(f0, f1, f2);
    k_post<<<BATCH, 1024>>>(f0, f1, f2, out);
}